// round 8
// baseline (speedup 1.0000x reference)
#include <cuda_runtime.h>
#include <cuda_bf16.h>
#include <cstdint>

// ===========================================================================
// Sparse conv encoder, mma.sync bf16 hi/lo x3.
// conv1 AND conv2: per-tap COMPACTED gather-GEMM; conv3 dense pipelined.
// R8: 32x64 warp tiles (4 warps/CTA) cut LDSM 25%; conv2 compaction (6x).
// ===========================================================================

#define MAXN 60032
#define NBMAX 256
#define KT1 27

__device__ __nv_bfloat16 g_x_hi[MAXN * 96];
__device__ __nv_bfloat16 g_x_lo[MAXN * 96];
__device__ __nv_bfloat16 g_f1_hi[MAXN * 64];
__device__ __nv_bfloat16 g_f1_lo[MAXN * 64];
__device__ __nv_bfloat16 g_f2_hi[MAXN * 64];
__device__ __nv_bfloat16 g_f2_lo[MAXN * 64];
__device__ __nv_bfloat16 g_w1_hi[27 * 96 * 64];
__device__ __nv_bfloat16 g_w1_lo[27 * 96 * 64];
__device__ __nv_bfloat16 g_w2_hi[8 * 64 * 64];
__device__ __nv_bfloat16 g_w2_lo[8 * 64 * 64];
__device__ __nv_bfloat16 g_w3_hi[27 * 64 * 64];
__device__ __nv_bfloat16 g_w3_lo[27 * 64 * 64];
__device__ float g_partial[128 * 128];
__device__ float g_st[128];

// compaction structures (reused by conv1 then conv2, sequentially)
__device__ int   g_mask[MAXN];
__device__ int   g_rowbase[MAXN];
__device__ int   g_taphist[KT1 * NBMAX];
__device__ int   g_tapblockbase[KT1 * NBMAX];
__device__ int   g_taptotal[KT1];
__device__ int   g_tapbase[KT1 + 1];
__device__ int   g_cntpart[NBMAX];
__device__ int   g_cntbase[NBMAX];
__device__ int   g_pairidx[KT1 * MAXN];
__device__ int   g_invpos[KT1 * MAXN];
__device__ float g_contrib[(size_t)KT1 * MAXN * 64];

__device__ __forceinline__ uint32_t smem_u32(const void* p) {
    uint32_t a;
    asm("{ .reg .u64 t; cvta.to.shared.u64 t, %1; cvt.u32.u64 %0, t; }"
        : "=r"(a) : "l"(p));
    return a;
}
__device__ __forceinline__ void cp16(uint32_t s, const void* g, int sz) {
    asm volatile("cp.async.cg.shared.global [%0], [%1], 16, %2;"
                 :: "r"(s), "l"(g), "r"(sz) : "memory");
}
__device__ __forceinline__ void cp_commit() {
    asm volatile("cp.async.commit_group;" ::: "memory");
}
template <int N>
__device__ __forceinline__ void cp_wait() {
    asm volatile("cp.async.wait_group %0;" :: "n"(N) : "memory");
}
__device__ __forceinline__ void ldsm_x4(uint32_t* r, uint32_t addr) {
    asm volatile("ldmatrix.sync.aligned.m8n8.x4.shared.b16 {%0,%1,%2,%3}, [%4];"
                 : "=r"(r[0]), "=r"(r[1]), "=r"(r[2]), "=r"(r[3]) : "r"(addr));
}
__device__ __forceinline__ void ldsm_x4_t(uint32_t* r, uint32_t addr) {
    asm volatile("ldmatrix.sync.aligned.m8n8.x4.trans.shared.b16 {%0,%1,%2,%3}, [%4];"
                 : "=r"(r[0]), "=r"(r[1]), "=r"(r[2]), "=r"(r[3]) : "r"(addr));
}
__device__ __forceinline__ void mma_bf16(float* d, const uint32_t* a, const uint32_t* b) {
    asm volatile(
        "mma.sync.aligned.m16n8k16.row.col.f32.bf16.bf16.f32 "
        "{%0,%1,%2,%3}, {%4,%5,%6,%7}, {%8,%9}, {%0,%1,%2,%3};"
        : "+f"(d[0]), "+f"(d[1]), "+f"(d[2]), "+f"(d[3])
        : "r"(a[0]), "r"(a[1]), "r"(a[2]), "r"(a[3]), "r"(b[0]), "r"(b[1]));
}
__device__ __forceinline__ int wscan_incl(int v, int lane) {
    #pragma unroll
    for (int o = 1; o < 32; o <<= 1) {
        const int u = __shfl_up_sync(0xffffffffu, v, o);
        if (lane >= o) v += u;
    }
    return v;
}

// ===========================================================================
// compaction prep (templated on tap count)
// ===========================================================================
template <int KT>
__global__ __launch_bounds__(256) void mask_kernel(
    const int* __restrict__ nmap, int n, int n_in)
{
    const int b = blockIdx.x, t = threadIdx.x;
    const int lane = t & 31, w = t >> 5;
    const int row = b * 256 + t;
    unsigned m = 0;
    if (row < n) {
        #pragma unroll
        for (int k = 0; k < KT; ++k)
            if (__ldg(&nmap[(size_t)row * KT + k]) < n_in) m |= 1u << k;
        g_mask[row] = (int)m;
    }
    const int cnt = __popc(m);

    __shared__ int hist[KT];
    if (t < KT) hist[t] = 0;
    __syncthreads();
    #pragma unroll
    for (int k = 0; k < KT; ++k) {
        const unsigned bal = __ballot_sync(0xffffffffu, (m >> k) & 1);
        if (lane == 0 && bal) atomicAdd(&hist[k], __popc(bal));
    }
    int v = cnt;
    #pragma unroll
    for (int o = 16; o > 0; o >>= 1) v += __shfl_down_sync(0xffffffffu, v, o);
    __shared__ int wsum[8];
    if (lane == 0) wsum[w] = v;
    __syncthreads();
    if (t == 0) {
        int s = 0;
        #pragma unroll
        for (int i = 0; i < 8; ++i) s += wsum[i];
        g_cntpart[b] = s;
    }
    if (t < KT) g_taphist[t * NBMAX + b] = hist[t];
}

template <int KT>
__global__ __launch_bounds__(896) void scan_kernel(int NB)
{
    const int tid = threadIdx.x, w = tid >> 5, lane = tid & 31;
    if (w < KT) {
        int s = 0;
        for (int b0 = 0; b0 < NB; b0 += 32) {
            const int b = b0 + lane;
            const int h = (b < NB) ? g_taphist[w * NBMAX + b] : 0;
            const int inc = wscan_incl(h, lane);
            if (b < NB) g_tapblockbase[w * NBMAX + b] = s + inc - h;
            s += __shfl_sync(0xffffffffu, inc, 31);
        }
        if (lane == 0) g_taptotal[w] = s;
    } else if (w == KT) {
        int s = 0;
        for (int b0 = 0; b0 < NB; b0 += 32) {
            const int b = b0 + lane;
            const int h = (b < NB) ? g_cntpart[b] : 0;
            const int inc = wscan_incl(h, lane);
            if (b < NB) g_cntbase[b] = s + inc - h;
            s += __shfl_sync(0xffffffffu, inc, 31);
        }
    }
    __syncthreads();
    if (w == 0) {
        const int v = (lane < KT) ? g_taptotal[lane] : 0;
        const int inc = wscan_incl(v, lane);
        if (lane <= KT) g_tapbase[lane] = inc - v;
    }
}

template <int KT>
__global__ __launch_bounds__(256) void emit_kernel(
    const int* __restrict__ nmap, int n)
{
    const int b = blockIdx.x, t = threadIdx.x;
    const int lane = t & 31, w = t >> 5;
    const int row = b * 256 + t;
    const unsigned m = (row < n) ? (unsigned)g_mask[row] : 0u;
    const int cnt = __popc(m);

    int v = cnt;
    #pragma unroll
    for (int o = 1; o < 32; o <<= 1) {
        const int u = __shfl_up_sync(0xffffffffu, v, o);
        if (lane >= o) v += u;
    }
    __shared__ int ws[8];
    if (lane == 31) ws[w] = v;
    __syncthreads();
    int wbase = 0;
    for (int i = 0; i < w; ++i) wbase += ws[i];
    const int rbase = g_cntbase[b] + wbase + v - cnt;
    if (row < n) g_rowbase[row] = rbase;

    __shared__ int wt[8];
    for (int k = 0; k < KT; ++k) {
        const int valid = (m >> k) & 1;
        const unsigned bal = __ballot_sync(0xffffffffu, valid);
        __syncthreads();
        if (lane == 0) wt[w] = __popc(bal);
        __syncthreads();
        int wb = 0;
        for (int i = 0; i < w; ++i) wb += wt[i];
        const int rank = wb + __popc(bal & ((1u << lane) - 1u));
        if (valid) {
            const int pos = g_tapbase[k] + g_tapblockbase[k * NBMAX + b] + rank;
            g_pairidx[pos] = __ldg(&nmap[(size_t)row * KT + k]);
            const int j = __popc(m & ((1u << k) - 1u));
            g_invpos[rbase + j] = pos;
        }
    }
}

// ===========================================================================
// Compact GEMM: one tap per CTA.y, 128 compacted rows x 64 cols.
// 4 warps (128 threads), warp tile 32 rows x 64 cols.
// ===========================================================================
template <int CIN>
__global__ __launch_bounds__(128) void conv_compact(
    const __nv_bfloat16* __restrict__ a_hi, const __nv_bfloat16* __restrict__ a_lo,
    const __nv_bfloat16* __restrict__ w_hi, const __nv_bfloat16* __restrict__ w_lo)
{
    constexpr int LDA = CIN + 8;
    constexpr int LDB = 72;
    constexpr int KSTEPS = CIN / 16;
    constexpr int CPR = CIN / 8;
    constexpr int A_HALVES = 128 * LDA;
    constexpr int B_HALVES = CIN * LDB;
    constexpr uint32_t OFF_ALO = (uint32_t)A_HALVES * 2;
    constexpr uint32_t OFF_BHI = (uint32_t)(2 * A_HALVES) * 2;
    constexpr uint32_t OFF_BLO = (uint32_t)(2 * A_HALVES + B_HALVES) * 2;

    const int k = blockIdx.y;
    const int tot = g_taptotal[k];
    const int tilestart = blockIdx.x * 128;
    if (tilestart >= tot) return;
    const int q0 = g_tapbase[k] + tilestart;

    extern __shared__ __align__(16) __nv_bfloat16 smem[];
    const uint32_t sb = smem_u32(smem);
    const int tid = threadIdx.x, wid = tid >> 5, lane = tid & 31;
    const int wm = wid * 32;
    const int lrow = lane & 15, lcol8 = (lane >> 4) * 8;

    #pragma unroll 2
    for (int i = tid; i < 2 * 128 * CPR; i += 128) {
        const int buf = i / (128 * CPR);
        const int j   = i % (128 * CPR);
        const int r   = j / CPR, c = j % CPR;
        const int ok  = tilestart + r < tot;
        const int idx = ok ? __ldg(&g_pairidx[q0 + r]) : 0;
        const __nv_bfloat16* src = (buf ? a_lo : a_hi) + (size_t)idx * CIN + c * 8;
        cp16(sb + (buf ? OFF_ALO : 0u) + (uint32_t)(r * LDA + c * 8) * 2,
             src, ok ? 16 : 0);
    }
    #pragma unroll 2
    for (int i = tid; i < 2 * CIN * 8; i += 128) {
        const int buf = i / (CIN * 8);
        const int j   = i % (CIN * 8);
        const int r   = j >> 3, c = j & 7;
        const __nv_bfloat16* src = (buf ? w_lo : w_hi)
            + (size_t)k * CIN * 64 + r * 64 + c * 8;
        cp16(sb + (buf ? OFF_BLO : OFF_BHI) + (uint32_t)(r * LDB + c * 8) * 2,
             src, 16);
    }
    cp_commit();
    cp_wait<0>();
    __syncthreads();

    float acc[2][8][4] = {};
    #pragma unroll
    for (int s = 0; s < KSTEPS; ++s) {
        uint32_t ah[2][4], al[2][4];
        #pragma unroll
        for (int mt = 0; mt < 2; ++mt) {
            const uint32_t off = (uint32_t)((wm + mt * 16 + lrow) * LDA
                                            + s * 16 + lcol8) * 2;
            ldsm_x4(ah[mt], sb + off);
            ldsm_x4(al[mt], sb + OFF_ALO + off);
        }
        uint32_t bh[4][4], bl[4][4];
        #pragma unroll
        for (int p = 0; p < 4; ++p) {
            const uint32_t off = (uint32_t)((s * 16 + lrow) * LDB
                                            + p * 16 + lcol8) * 2;
            ldsm_x4_t(bh[p], sb + OFF_BHI + off);
            ldsm_x4_t(bl[p], sb + OFF_BLO + off);
        }
        #pragma unroll
        for (int mt = 0; mt < 2; ++mt)
            #pragma unroll
            for (int nt = 0; nt < 8; ++nt) {
                const uint32_t* Bh = &bh[nt >> 1][(nt & 1) * 2];
                const uint32_t* Bl = &bl[nt >> 1][(nt & 1) * 2];
                mma_bf16(acc[mt][nt], ah[mt], Bh);
                mma_bf16(acc[mt][nt], ah[mt], Bl);
                mma_bf16(acc[mt][nt], al[mt], Bh);
            }
    }

    #pragma unroll
    for (int mt = 0; mt < 2; ++mt)
        #pragma unroll
        for (int nt = 0; nt < 8; ++nt)
            #pragma unroll
            for (int h = 0; h < 2; ++h) {
                const int rl = wm + mt * 16 + h * 8 + (lane >> 2);
                if (tilestart + rl < tot) {
                    const int col = nt * 8 + (lane & 3) * 2;
                    float2 v;
                    v.x = acc[mt][nt][h * 2];
                    v.y = acc[mt][nt][h * 2 + 1];
                    *(float2*)(g_contrib + (size_t)(q0 + rl) * 64 + col) = v;
                }
            }
}

// reduce per-row contributions -> out (bias + leaky + bf16 hi/lo split)
__global__ __launch_bounds__(256) void reduce_kernel(
    const float* __restrict__ bias, int n,
    __nv_bfloat16* __restrict__ o_hi, __nv_bfloat16* __restrict__ o_lo)
{
    const int row = blockIdx.x * 8 + (threadIdx.x >> 5);
    if (row >= n) return;
    const int lane = threadIdx.x & 31;
    const int cnt  = __popc((unsigned)g_mask[row]);
    const int base = g_rowbase[row];
    const int c0   = lane * 2;
    float s0 = __ldg(&bias[c0]), s1 = __ldg(&bias[c0 + 1]);
    for (int j = 0; j < cnt; ++j) {
        const int p = __ldg(&g_invpos[base + j]);
        const float2 v = *(const float2*)(g_contrib + (size_t)p * 64 + c0);
        s0 += v.x; s1 += v.y;
    }
    s0 = s0 >= 0.f ? s0 : 0.1f * s0;
    s1 = s1 >= 0.f ? s1 : 0.1f * s1;
    __nv_bfloat162 hh, ll;
    hh.x = __float2bfloat16_rn(s0);
    hh.y = __float2bfloat16_rn(s1);
    ll.x = __float2bfloat16_rn(s0 - __bfloat162float(hh.x));
    ll.y = __float2bfloat16_rn(s1 - __bfloat162float(hh.y));
    *(uint32_t*)(o_hi + (size_t)row * 64 + c0) = *(uint32_t*)&hh;
    *(uint32_t*)(o_lo + (size_t)row * 64 + c0) = *(uint32_t*)&ll;
}

// ===========================================================================
// Dense gather-GEMM (conv3): 2-stage cp.async tap pipeline, 4 warps, 32x64
// ===========================================================================
template <int CIN, int KT>
__global__ __launch_bounds__(128) void sconv_dense(
    const __nv_bfloat16* __restrict__ a_hi, const __nv_bfloat16* __restrict__ a_lo,
    int n_in, const int* __restrict__ nmap, int n_out,
    const __nv_bfloat16* __restrict__ w_hi, const __nv_bfloat16* __restrict__ w_lo,
    const float* __restrict__ bias, float* __restrict__ o_f32)
{
    constexpr int LDA = CIN + 8;
    constexpr int LDB = 72;
    constexpr int KSTEPS = CIN / 16;
    constexpr int CPR = CIN / 8;
    constexpr int A_HALVES = 128 * LDA;
    constexpr int B_HALVES = CIN * LDB;
    constexpr uint32_t OFF_ALO = (uint32_t)A_HALVES * 2;
    constexpr uint32_t OFF_BHI = (uint32_t)(2 * A_HALVES) * 2;
    constexpr uint32_t OFF_BLO = (uint32_t)(2 * A_HALVES + B_HALVES) * 2;
    constexpr uint32_t STAGE   = (uint32_t)(2 * A_HALVES + 2 * B_HALVES) * 2;

    extern __shared__ __align__(16) __nv_bfloat16 smem[];
    const uint32_t sb = smem_u32(smem);

    const int tid  = threadIdx.x;
    const int wid  = tid >> 5;
    const int lane = tid & 31;
    const int row0 = blockIdx.x * 128;
    const int wm   = wid * 32;
    const int lrow = lane & 15, lcol8 = (lane >> 4) * 8;

    float acc[2][8][4] = {};

    auto prefetch = [&](int t, uint32_t stoff) {
        #pragma unroll 2
        for (int i = tid; i < 2 * 128 * CPR; i += 128) {
            const int buf = i / (128 * CPR);
            const int j   = i % (128 * CPR);
            const int r   = j / CPR, c = j % CPR;
            const int rr  = row0 + r;
            int idx = n_in;
            if (rr < n_out) idx = __ldg(&nmap[(size_t)rr * KT + t]);
            const int ok = idx < n_in;
            const __nv_bfloat16* src = (buf ? a_lo : a_hi)
                + (size_t)(ok ? idx : 0) * CIN + c * 8;
            cp16(sb + stoff + (buf ? OFF_ALO : 0u)
                 + (uint32_t)(r * LDA + c * 8) * 2, src, ok ? 16 : 0);
        }
        #pragma unroll 2
        for (int i = tid; i < 2 * CIN * 8; i += 128) {
            const int buf = i / (CIN * 8);
            const int j   = i % (CIN * 8);
            const int r   = j >> 3, c = j & 7;
            const __nv_bfloat16* src = (buf ? w_lo : w_hi)
                + (size_t)t * CIN * 64 + r * 64 + c * 8;
            cp16(sb + stoff + (buf ? OFF_BLO : OFF_BHI)
                 + (uint32_t)(r * LDB + c * 8) * 2, src, 16);
        }
    };

    prefetch(0, 0);
    cp_commit();

    for (int t = 0; t < KT; ++t) {
        const uint32_t stoff = (t & 1) ? STAGE : 0u;
        if (t + 1 < KT) {
            prefetch(t + 1, (t & 1) ? 0u : STAGE);
            cp_commit();
            cp_wait<1>();
        } else {
            cp_wait<0>();
        }
        __syncthreads();

        #pragma unroll
        for (int s = 0; s < KSTEPS; ++s) {
            uint32_t ah[2][4], al[2][4];
            #pragma unroll
            for (int mt = 0; mt < 2; ++mt) {
                const uint32_t off = (uint32_t)((wm + mt * 16 + lrow) * LDA
                                                + s * 16 + lcol8) * 2;
                ldsm_x4(ah[mt], sb + stoff + off);
                ldsm_x4(al[mt], sb + stoff + OFF_ALO + off);
            }
            uint32_t bh[4][4], bl[4][4];
            #pragma unroll
            for (int p = 0; p < 4; ++p) {
                const uint32_t off = (uint32_t)((s * 16 + lrow) * LDB
                                                + p * 16 + lcol8) * 2;
                ldsm_x4_t(bh[p], sb + stoff + OFF_BHI + off);
                ldsm_x4_t(bl[p], sb + stoff + OFF_BLO + off);
            }
            #pragma unroll
            for (int mt = 0; mt < 2; ++mt)
                #pragma unroll
                for (int nt = 0; nt < 8; ++nt) {
                    const uint32_t* Bh = &bh[nt >> 1][(nt & 1) * 2];
                    const uint32_t* Bl = &bl[nt >> 1][(nt & 1) * 2];
                    mma_bf16(acc[mt][nt], ah[mt], Bh);
                    mma_bf16(acc[mt][nt], ah[mt], Bl);
                    mma_bf16(acc[mt][nt], al[mt], Bh);
                }
        }
        __syncthreads();
    }

    #pragma unroll
    for (int mt = 0; mt < 2; ++mt)
        #pragma unroll
        for (int nt = 0; nt < 8; ++nt)
            #pragma unroll
            for (int h = 0; h < 2; ++h) {
                const int row = row0 + wm + mt * 16 + h * 8 + (lane >> 2);
                if (row >= n_out) continue;
                const int col = nt * 8 + (lane & 3) * 2;
                float2 v;
                v.x = acc[mt][nt][h * 2]     + __ldg(&bias[col]);
                v.y = acc[mt][nt][h * 2 + 1] + __ldg(&bias[col + 1]);
                *(float2*)(o_f32 + (size_t)row * 64 + col) = v;
            }
}

// ---------------------------------------------------------------------------
__global__ __launch_bounds__(256) void split_kernel(
    const float* __restrict__ src, __nv_bfloat16* __restrict__ hi,
    __nv_bfloat16* __restrict__ lo, int n)
{
    for (int i = blockIdx.x * 256 + threadIdx.x; i < n; i += gridDim.x * 256) {
        const float v = src[i];
        const __nv_bfloat16 h = __float2bfloat16_rn(v);
        hi[i] = h;
        lo[i] = __float2bfloat16_rn(v - __bfloat162float(h));
    }
}

// merged weight split: W1 | W2 | W3
__global__ __launch_bounds__(256) void splitw_kernel(
    const float* __restrict__ W1, __nv_bfloat16* __restrict__ h1, __nv_bfloat16* __restrict__ l1, int n1,
    const float* __restrict__ W2, __nv_bfloat16* __restrict__ h2, __nv_bfloat16* __restrict__ l2, int n2,
    const float* __restrict__ W3, __nv_bfloat16* __restrict__ h3, __nv_bfloat16* __restrict__ l3, int n3)
{
    const int total = n1 + n2 + n3;
    for (int i = blockIdx.x * 256 + threadIdx.x; i < total; i += gridDim.x * 256) {
        const float* s; __nv_bfloat16 *hp, *lp; int j;
        if (i < n1)           { s = W1; hp = h1; lp = l1; j = i; }
        else if (i < n1 + n2) { s = W2; hp = h2; lp = l2; j = i - n1; }
        else                  { s = W3; hp = h3; lp = l3; j = i - n1 - n2; }
        const float v = s[j];
        const __nv_bfloat16 h = __float2bfloat16_rn(v);
        hp[j] = h;
        lp[j] = __float2bfloat16_rn(v - __bfloat162float(h));
    }
}

__global__ __launch_bounds__(256) void bn_partial_kernel(
    const __nv_bfloat16* __restrict__ fh, const __nv_bfloat16* __restrict__ fl,
    int n2, float* __restrict__ partial)
{
    const int tid = threadIdx.x;
    const int c = tid & 63;
    const int sub = tid >> 6;
    float s = 0.f, s2 = 0.f;
    for (int r = blockIdx.x * 4 + sub; r < n2; r += gridDim.x * 4) {
        const size_t i = (size_t)r * 64 + c;
        const float v = __bfloat162float(fh[i]) + __bfloat162float(fl[i]);
        s += v; s2 += v * v;
    }
    __shared__ float sh[256], sh2[256];
    sh[tid] = s; sh2[tid] = s2;
    __syncthreads();
    if (tid < 64) {
        s  = sh[tid]  + sh[tid + 64]  + sh[tid + 128]  + sh[tid + 192];
        s2 = sh2[tid] + sh2[tid + 64] + sh2[tid + 128] + sh2[tid + 192];
        partial[blockIdx.x * 128 + tid]      = s;
        partial[blockIdx.x * 128 + 64 + tid] = s2;
    }
}

__global__ void bn_finalize_kernel(
    const float* __restrict__ partial, int G, int n2,
    const float* __restrict__ gamma, const float* __restrict__ beta,
    const float* __restrict__ scale, float* __restrict__ st)
{
    const int c = threadIdx.x;
    float s = 0.f, s2 = 0.f;
    for (int g = 0; g < G; ++g) {
        s  += partial[g * 128 + c];
        s2 += partial[g * 128 + 64 + c];
    }
    const float inv_n = 1.0f / (float)n2;
    const float mu  = s * inv_n;
    const float var = fmaxf(s2 * inv_n - mu * mu, 0.f);
    const float r   = rsqrtf(var + 1e-5f);
    const float sc  = scale[0];
    st[c]      = gamma[c] * r * sc;
    st[64 + c] = (beta[c] - mu * gamma[c] * r) * sc;
}

__global__ __launch_bounds__(256) void bn_apply_kernel(
    __nv_bfloat16* __restrict__ fh, __nv_bfloat16* __restrict__ fl,
    int n2, const float* __restrict__ st)
{
    const int i = blockIdx.x * 256 + threadIdx.x;
    if (i < n2 * 64) {
        const int c = i & 63;
        const float v = fmaf(__bfloat162float(fh[i]) + __bfloat162float(fl[i]),
                             st[c], st[64 + c]);
        const __nv_bfloat16 h = __float2bfloat16_rn(v);
        fh[i] = h;
        fl[i] = __float2bfloat16_rn(v - __bfloat162float(h));
    }
}

// ---------------------------------------------------------------------------
extern "C" void kernel_launch(void* const* d_in, const int* in_sizes, int n_in_arrs,
                              void* d_out, int out_size)
{
    const float* x     = (const float*)d_in[0];
    const float* W1    = (const float*)d_in[1];
    const float* b1    = (const float*)d_in[2];
    const float* W2    = (const float*)d_in[3];
    const float* b2    = (const float*)d_in[4];
    const float* W3    = (const float*)d_in[5];
    const float* b3    = (const float*)d_in[6];
    const float* gamma = (const float*)d_in[7];
    const float* beta  = (const float*)d_in[8];
    const float* scale = (const float*)d_in[9];
    const int* nmap1   = (const int*)d_in[10];
    const int* nmap2   = (const int*)d_in[11];
    const int* nmap3   = (const int*)d_in[12];

    const int N   = in_sizes[0] / 96;
    const int N2  = in_sizes[11] / 8;
    const int NB  = (N + 255) / 256;
    const int NB2 = (N2 + 255) / 256;

    __nv_bfloat16 *xh, *xl, *f1h, *f1l, *f2h, *f2l, *w1h, *w1l, *w2h, *w2l, *w3h, *w3l;
    float *partial, *st;
    cudaGetSymbolAddress((void**)&xh, g_x_hi);   cudaGetSymbolAddress((void**)&xl, g_x_lo);
    cudaGetSymbolAddress((void**)&f1h, g_f1_hi); cudaGetSymbolAddress((void**)&f1l, g_f1_lo);
    cudaGetSymbolAddress((void**)&f2h, g_f2_hi); cudaGetSymbolAddress((void**)&f2l, g_f2_lo);
    cudaGetSymbolAddress((void**)&w1h, g_w1_hi); cudaGetSymbolAddress((void**)&w1l, g_w1_lo);
    cudaGetSymbolAddress((void**)&w2h, g_w2_hi); cudaGetSymbolAddress((void**)&w2l, g_w2_lo);
    cudaGetSymbolAddress((void**)&w3h, g_w3_hi); cudaGetSymbolAddress((void**)&w3l, g_w3_lo);
    cudaGetSymbolAddress((void**)&partial, g_partial);
    cudaGetSymbolAddress((void**)&st, g_st);

    split_kernel<<<512, 256>>>(x, xh, xl, N * 96);
    splitw_kernel<<<256, 256>>>(W1, w1h, w1l, 27 * 96 * 64,
                                W2, w2h, w2l, 8 * 64 * 64,
                                W3, w3h, w3l, 27 * 64 * 64);

    // ---- conv1: compacted (27 taps, 96ch) ----
    mask_kernel<KT1><<<NB, 256>>>(nmap1, N, N);
    scan_kernel<KT1><<<1, (KT1 + 1) * 32>>>(NB);
    emit_kernel<KT1><<<NB, 256>>>(nmap1, N);
    {
        constexpr int smem = (2 * 128 * 104 + 2 * 96 * 72) * 2;   // 80,896 B
        cudaFuncSetAttribute(conv_compact<96>,
                             cudaFuncAttributeMaxDynamicSharedMemorySize, smem);
        dim3 grid((N + 127) / 128, KT1);
        conv_compact<96><<<grid, 128, smem>>>(xh, xl, w1h, w1l);
    }
    reduce_kernel<<<(N + 7) / 8, 256>>>(b1, N, f1h, f1l);

    // ---- conv2: compacted (8 taps, 64ch) ----
    mask_kernel<8><<<NB2, 256>>>(nmap2, N2, N);
    scan_kernel<8><<<1, 9 * 32>>>(NB2);
    emit_kernel<8><<<NB2, 256>>>(nmap2, N2);
    {
        constexpr int smem = (2 * 128 * 72 + 2 * 64 * 72) * 2;    // 55,296 B
        cudaFuncSetAttribute(conv_compact<64>,
                             cudaFuncAttributeMaxDynamicSharedMemorySize, smem);
        dim3 grid((N2 + 127) / 128, 8);
        conv_compact<64><<<grid, 128, smem>>>(f1h, f1l, w2h, w2l);
    }
    reduce_kernel<<<(N2 + 7) / 8, 256>>>(b2, N2, f2h, f2l);

    // ---- batch norm + scale ----
    {
        const int G = 120;
        bn_partial_kernel<<<G, 256>>>(f2h, f2l, N2, partial);
        bn_finalize_kernel<<<1, 64>>>(partial, G, N2, gamma, beta, scale, st);
        bn_apply_kernel<<<(N2 * 64 + 255) / 256, 256>>>(f2h, f2l, N2, st);
    }
    // ---- conv3: dense, 27 taps, fp32 out ----
    {
        constexpr int stage = (2 * 128 * 72 + 2 * 64 * 72) * 2;
        constexpr int smem  = 2 * stage;                          // 110,592 B
        cudaFuncSetAttribute(sconv_dense<64, 27>,
                             cudaFuncAttributeMaxDynamicSharedMemorySize, smem);
        sconv_dense<64, 27><<<(N2 + 127) / 128, 128, smem>>>(
            f2h, f2l, N2, nmap3, N2, w3h, w3l, b3, (float*)d_out);
    }
}

// round 9
// speedup vs baseline: 1.2092x; 1.2092x over previous
#include <cuda_runtime.h>
#include <cuda_bf16.h>
#include <cstdint>

// ===========================================================================
// Sparse conv encoder, mma.sync bf16 hi/lo x3.
// conv1: per-tap COMPACTED gather-GEMM (single fused atomic-emit prep);
// conv2/conv3: dense cp.async double-buffered tap pipeline. (R7 GEMM configs)
// ===========================================================================

#define MAXN 60032
#define KT1 27

__device__ __nv_bfloat16 g_x_hi[MAXN * 96];
__device__ __nv_bfloat16 g_x_lo[MAXN * 96];
__device__ __nv_bfloat16 g_f1_hi[MAXN * 64];
__device__ __nv_bfloat16 g_f1_lo[MAXN * 64];
__device__ __nv_bfloat16 g_f2_hi[MAXN * 64];
__device__ __nv_bfloat16 g_f2_lo[MAXN * 64];
__device__ __nv_bfloat16 g_w1_hi[27 * 96 * 64];
__device__ __nv_bfloat16 g_w1_lo[27 * 96 * 64];
__device__ __nv_bfloat16 g_w2_hi[8 * 64 * 64];
__device__ __nv_bfloat16 g_w2_lo[8 * 64 * 64];
__device__ __nv_bfloat16 g_w3_hi[27 * 64 * 64];
__device__ __nv_bfloat16 g_w3_lo[27 * 64 * 64];
__device__ float g_partial[128 * 128];
__device__ float g_st[128];

// conv1 compaction (fixed-stride per-tap regions: tap k owns [k*MAXN, ...))
__device__ int   g_mask[MAXN];
__device__ int   g_tapcnt[KT1];
__device__ int   g_pairidx[KT1 * MAXN];
__device__ int   g_invpos[KT1 * MAXN];     // [j*MAXN + row]
__device__ float g_contrib[(size_t)KT1 * MAXN * 64];

__device__ __forceinline__ uint32_t smem_u32(const void* p) {
    uint32_t a;
    asm("{ .reg .u64 t; cvta.to.shared.u64 t, %1; cvt.u32.u64 %0, t; }"
        : "=r"(a) : "l"(p));
    return a;
}
__device__ __forceinline__ void cp16(uint32_t s, const void* g, int sz) {
    asm volatile("cp.async.cg.shared.global [%0], [%1], 16, %2;"
                 :: "r"(s), "l"(g), "r"(sz) : "memory");
}
__device__ __forceinline__ void cp_commit() {
    asm volatile("cp.async.commit_group;" ::: "memory");
}
template <int N>
__device__ __forceinline__ void cp_wait() {
    asm volatile("cp.async.wait_group %0;" :: "n"(N) : "memory");
}
__device__ __forceinline__ void ldsm_x4(uint32_t* r, uint32_t addr) {
    asm volatile("ldmatrix.sync.aligned.m8n8.x4.shared.b16 {%0,%1,%2,%3}, [%4];"
                 : "=r"(r[0]), "=r"(r[1]), "=r"(r[2]), "=r"(r[3]) : "r"(addr));
}
__device__ __forceinline__ void ldsm_x4_t(uint32_t* r, uint32_t addr) {
    asm volatile("ldmatrix.sync.aligned.m8n8.x4.trans.shared.b16 {%0,%1,%2,%3}, [%4];"
                 : "=r"(r[0]), "=r"(r[1]), "=r"(r[2]), "=r"(r[3]) : "r"(addr));
}
__device__ __forceinline__ void mma_bf16(float* d, const uint32_t* a, const uint32_t* b) {
    asm volatile(
        "mma.sync.aligned.m16n8k16.row.col.f32.bf16.bf16.f32 "
        "{%0,%1,%2,%3}, {%4,%5,%6,%7}, {%8,%9}, {%0,%1,%2,%3};"
        : "+f"(d[0]), "+f"(d[1]), "+f"(d[2]), "+f"(d[3])
        : "r"(a[0]), "r"(a[1]), "r"(a[2]), "r"(a[3]), "r"(b[0]), "r"(b[1]));
}

// ===========================================================================
// Fused compaction: mask + per-block histogram + atomic block-base + emit.
// Pair placement order varies with block arrival, but every output value is
// row-independent, so d_out is replay-deterministic.
// ===========================================================================
__global__ __launch_bounds__(256) void emit_fused(
    const int* __restrict__ nmap, int n, int n_in)
{
    const int t = threadIdx.x, lane = t & 31, w = t >> 5;
    const int row = blockIdx.x * 256 + t;

    int idxs[KT1];
    unsigned m = 0;
    if (row < n) {
        #pragma unroll
        for (int k = 0; k < KT1; ++k) {
            idxs[k] = __ldg(&nmap[(size_t)row * KT1 + k]);
            if (idxs[k] < n_in) m |= 1u << k;
        }
        g_mask[row] = (int)m;
    }

    // per-block histogram
    __shared__ int hist[KT1], base[KT1], wt[KT1][8];
    if (t < KT1) hist[t] = 0;
    __syncthreads();
    #pragma unroll
    for (int k = 0; k < KT1; ++k) {
        const unsigned bal = __ballot_sync(0xffffffffu, (m >> k) & 1);
        if (lane == 0) { wt[k][w] = __popc(bal); if (bal) atomicAdd(&hist[k], __popc(bal)); }
    }
    __syncthreads();
    // one global atomic per tap per block claims a contiguous range
    if (t < KT1) base[t] = atomicAdd(&g_tapcnt[t], hist[t]);
    __syncthreads();

    int j = 0;
    #pragma unroll
    for (int k = 0; k < KT1; ++k) {
        const int valid = (m >> k) & 1;
        const unsigned bal = __ballot_sync(0xffffffffu, valid);
        if (valid) {
            int wb = 0;
            #pragma unroll
            for (int i = 0; i < 8; ++i) if (i < w) wb += wt[k][i];
            const int rank = wb + __popc(bal & ((1u << lane) - 1u));
            const int pos  = k * MAXN + base[k] + rank;
            g_pairidx[pos] = idxs[k];
            g_invpos[(size_t)j * MAXN + row] = pos;
            ++j;
        }
    }
}

// ===========================================================================
// conv1 compact GEMM: one tap per CTA.y, 128 compacted rows x 64 cols,
// 8 warps (4x2), warp tile 32x32.  (R7 config)
// ===========================================================================
__global__ __launch_bounds__(256) void conv1_compact(
    const __nv_bfloat16* __restrict__ a_hi, const __nv_bfloat16* __restrict__ a_lo,
    const __nv_bfloat16* __restrict__ w_hi, const __nv_bfloat16* __restrict__ w_lo)
{
    constexpr int CIN = 96;
    constexpr int LDA = CIN + 8;
    constexpr int LDB = 72;
    constexpr int KSTEPS = CIN / 16;
    constexpr int CPR = CIN / 8;
    constexpr int A_HALVES = 128 * LDA;
    constexpr int B_HALVES = CIN * LDB;
    constexpr uint32_t OFF_ALO = (uint32_t)A_HALVES * 2;
    constexpr uint32_t OFF_BHI = (uint32_t)(2 * A_HALVES) * 2;
    constexpr uint32_t OFF_BLO = (uint32_t)(2 * A_HALVES + B_HALVES) * 2;

    const int k = blockIdx.y;
    const int tot = g_tapcnt[k];
    const int tilestart = blockIdx.x * 128;
    if (tilestart >= tot) return;
    const int q0 = k * MAXN + tilestart;

    extern __shared__ __align__(16) __nv_bfloat16 smem[];
    const uint32_t sb = smem_u32(smem);
    const int tid = threadIdx.x, wid = tid >> 5, lane = tid & 31;
    const int wm = (wid >> 1) * 32, wn = (wid & 1) * 32;
    const int lrow = lane & 15, lcol8 = (lane >> 4) * 8;

    #pragma unroll 2
    for (int i = tid; i < 2 * 128 * CPR; i += 256) {
        const int buf = i / (128 * CPR);
        const int j   = i % (128 * CPR);
        const int r   = j / CPR, c = j % CPR;
        const int ok  = tilestart + r < tot;
        const int idx = ok ? __ldg(&g_pairidx[q0 + r]) : 0;
        const __nv_bfloat16* src = (buf ? a_lo : a_hi) + (size_t)idx * CIN + c * 8;
        cp16(sb + (buf ? OFF_ALO : 0u) + (uint32_t)(r * LDA + c * 8) * 2,
             src, ok ? 16 : 0);
    }
    #pragma unroll 2
    for (int i = tid; i < 2 * CIN * 8; i += 256) {
        const int buf = i / (CIN * 8);
        const int j   = i % (CIN * 8);
        const int r   = j >> 3, c = j & 7;
        const __nv_bfloat16* src = (buf ? w_lo : w_hi)
            + (size_t)k * CIN * 64 + r * 64 + c * 8;
        cp16(sb + (buf ? OFF_BLO : OFF_BHI) + (uint32_t)(r * LDB + c * 8) * 2,
             src, 16);
    }
    cp_commit();
    cp_wait<0>();
    __syncthreads();

    float acc[2][4][4] = {};
    #pragma unroll
    for (int s = 0; s < KSTEPS; ++s) {
        uint32_t ah[2][4], al[2][4];
        #pragma unroll
        for (int mt = 0; mt < 2; ++mt) {
            const uint32_t off = (uint32_t)((wm + mt * 16 + lrow) * LDA
                                            + s * 16 + lcol8) * 2;
            ldsm_x4(ah[mt], sb + off);
            ldsm_x4(al[mt], sb + OFF_ALO + off);
        }
        uint32_t bh[2][4], bl[2][4];
        #pragma unroll
        for (int p = 0; p < 2; ++p) {
            const uint32_t off = (uint32_t)((s * 16 + lrow) * LDB
                                            + wn + p * 16 + lcol8) * 2;
            ldsm_x4_t(bh[p], sb + OFF_BHI + off);
            ldsm_x4_t(bl[p], sb + OFF_BLO + off);
        }
        #pragma unroll
        for (int mt = 0; mt < 2; ++mt)
            #pragma unroll
            for (int nt = 0; nt < 4; ++nt) {
                const uint32_t* Bh = &bh[nt >> 1][(nt & 1) * 2];
                const uint32_t* Bl = &bl[nt >> 1][(nt & 1) * 2];
                mma_bf16(acc[mt][nt], ah[mt], Bh);
                mma_bf16(acc[mt][nt], ah[mt], Bl);
                mma_bf16(acc[mt][nt], al[mt], Bh);
            }
    }

    #pragma unroll
    for (int mt = 0; mt < 2; ++mt)
        #pragma unroll
        for (int nt = 0; nt < 4; ++nt)
            #pragma unroll
            for (int h = 0; h < 2; ++h) {
                const int rl = wm + mt * 16 + h * 8 + (lane >> 2);
                if (tilestart + rl < tot) {
                    const int col = wn + nt * 8 + (lane & 3) * 2;
                    float2 v;
                    v.x = acc[mt][nt][h * 2];
                    v.y = acc[mt][nt][h * 2 + 1];
                    *(float2*)(g_contrib + (size_t)(q0 + rl) * 64 + col) = v;
                }
            }
}

// reduce per-row contributions -> f1 (fixed ascending-tap order)
__global__ __launch_bounds__(256) void reduce1_kernel(
    const float* __restrict__ bias, int n,
    __nv_bfloat16* __restrict__ o_hi, __nv_bfloat16* __restrict__ o_lo)
{
    const int row = blockIdx.x * 8 + (threadIdx.x >> 5);
    if (row >= n) return;
    const int lane = threadIdx.x & 31;
    const int cnt  = __popc((unsigned)g_mask[row]);
    const int c0   = lane * 2;
    float s0 = __ldg(&bias[c0]), s1 = __ldg(&bias[c0 + 1]);
    for (int j = 0; j < cnt; ++j) {
        const int p = __ldg(&g_invpos[(size_t)j * MAXN + row]);
        const float2 v = *(const float2*)(g_contrib + (size_t)p * 64 + c0);
        s0 += v.x; s1 += v.y;
    }
    s0 = s0 >= 0.f ? s0 : 0.1f * s0;
    s1 = s1 >= 0.f ? s1 : 0.1f * s1;
    __nv_bfloat162 hh, ll;
    hh.x = __float2bfloat16_rn(s0);
    hh.y = __float2bfloat16_rn(s1);
    ll.x = __float2bfloat16_rn(s0 - __bfloat162float(hh.x));
    ll.y = __float2bfloat16_rn(s1 - __bfloat162float(hh.y));
    *(uint32_t*)(o_hi + (size_t)row * 64 + c0) = *(uint32_t*)&hh;
    *(uint32_t*)(o_lo + (size_t)row * 64 + c0) = *(uint32_t*)&ll;
}

// ===========================================================================
// Dense gather-GEMM (conv2/conv3): 2-stage cp.async pipeline, 8 warps (4x2)
// ===========================================================================
template <int CIN, int KT, bool LEAKY, bool SPLIT_OUT>
__global__ __launch_bounds__(256) void sconv_mma(
    const __nv_bfloat16* __restrict__ a_hi, const __nv_bfloat16* __restrict__ a_lo,
    int n_in, const int* __restrict__ nmap, int n_out,
    const __nv_bfloat16* __restrict__ w_hi, const __nv_bfloat16* __restrict__ w_lo,
    const float* __restrict__ bias,
    __nv_bfloat16* __restrict__ o_hi, __nv_bfloat16* __restrict__ o_lo,
    float* __restrict__ o_f32)
{
    constexpr int LDA = CIN + 8;
    constexpr int LDB = 72;
    constexpr int KSTEPS = CIN / 16;
    constexpr int CPR = CIN / 8;
    constexpr int A_HALVES = 128 * LDA;
    constexpr int B_HALVES = CIN * LDB;
    constexpr uint32_t OFF_ALO = (uint32_t)A_HALVES * 2;
    constexpr uint32_t OFF_BHI = (uint32_t)(2 * A_HALVES) * 2;
    constexpr uint32_t OFF_BLO = (uint32_t)(2 * A_HALVES + B_HALVES) * 2;
    constexpr uint32_t STAGE   = (uint32_t)(2 * A_HALVES + 2 * B_HALVES) * 2;

    extern __shared__ __align__(16) __nv_bfloat16 smem[];
    const uint32_t sb = smem_u32(smem);

    const int tid  = threadIdx.x;
    const int wid  = tid >> 5;
    const int lane = tid & 31;
    const int row0 = blockIdx.x * 128;
    const int wm   = (wid >> 1) * 32;
    const int wn   = (wid & 1) * 32;
    const int lrow = lane & 15, lcol8 = (lane >> 4) * 8;

    float acc[2][4][4] = {};

    auto prefetch = [&](int t, uint32_t stoff) {
        #pragma unroll 2
        for (int i = tid; i < 2 * 128 * CPR; i += 256) {
            const int buf = i / (128 * CPR);
            const int j   = i % (128 * CPR);
            const int r   = j / CPR, c = j % CPR;
            const int rr  = row0 + r;
            int idx = n_in;
            if (rr < n_out) idx = __ldg(&nmap[(size_t)rr * KT + t]);
            const int ok = idx < n_in;
            const __nv_bfloat16* src = (buf ? a_lo : a_hi)
                + (size_t)(ok ? idx : 0) * CIN + c * 8;
            cp16(sb + stoff + (buf ? OFF_ALO : 0u)
                 + (uint32_t)(r * LDA + c * 8) * 2, src, ok ? 16 : 0);
        }
        #pragma unroll 2
        for (int i = tid; i < 2 * CIN * 8; i += 256) {
            const int buf = i / (CIN * 8);
            const int j   = i % (CIN * 8);
            const int r   = j >> 3, c = j & 7;
            const __nv_bfloat16* src = (buf ? w_lo : w_hi)
                + (size_t)t * CIN * 64 + r * 64 + c * 8;
            cp16(sb + stoff + (buf ? OFF_BLO : OFF_BHI)
                 + (uint32_t)(r * LDB + c * 8) * 2, src, 16);
        }
    };

    prefetch(0, 0);
    cp_commit();

    for (int t = 0; t < KT; ++t) {
        const uint32_t stoff = (t & 1) ? STAGE : 0u;
        if (t + 1 < KT) {
            prefetch(t + 1, (t & 1) ? 0u : STAGE);
            cp_commit();
            cp_wait<1>();
        } else {
            cp_wait<0>();
        }
        __syncthreads();

        #pragma unroll
        for (int s = 0; s < KSTEPS; ++s) {
            uint32_t ah[2][4], al[2][4];
            #pragma unroll
            for (int mt = 0; mt < 2; ++mt) {
                const uint32_t off = (uint32_t)((wm + mt * 16 + lrow) * LDA
                                                + s * 16 + lcol8) * 2;
                ldsm_x4(ah[mt], sb + stoff + off);
                ldsm_x4(al[mt], sb + stoff + OFF_ALO + off);
            }
            uint32_t bh[2][4], bl[2][4];
            #pragma unroll
            for (int p = 0; p < 2; ++p) {
                const uint32_t off = (uint32_t)((s * 16 + lrow) * LDB
                                                + wn + p * 16 + lcol8) * 2;
                ldsm_x4_t(bh[p], sb + stoff + OFF_BHI + off);
                ldsm_x4_t(bl[p], sb + stoff + OFF_BLO + off);
            }
            #pragma unroll
            for (int mt = 0; mt < 2; ++mt)
                #pragma unroll
                for (int nt = 0; nt < 4; ++nt) {
                    const uint32_t* Bh = &bh[nt >> 1][(nt & 1) * 2];
                    const uint32_t* Bl = &bl[nt >> 1][(nt & 1) * 2];
                    mma_bf16(acc[mt][nt], ah[mt], Bh);
                    mma_bf16(acc[mt][nt], ah[mt], Bl);
                    mma_bf16(acc[mt][nt], al[mt], Bh);
                }
        }
        __syncthreads();
    }

    #pragma unroll
    for (int mt = 0; mt < 2; ++mt)
        #pragma unroll
        for (int nt = 0; nt < 4; ++nt)
            #pragma unroll
            for (int h = 0; h < 2; ++h) {
                const int row = row0 + wm + mt * 16 + h * 8 + (lane >> 2);
                if (row >= n_out) continue;
                const int col = wn + nt * 8 + (lane & 3) * 2;
                float v0 = acc[mt][nt][h * 2]     + __ldg(&bias[col]);
                float v1 = acc[mt][nt][h * 2 + 1] + __ldg(&bias[col + 1]);
                if (LEAKY) {
                    v0 = v0 >= 0.f ? v0 : 0.1f * v0;
                    v1 = v1 >= 0.f ? v1 : 0.1f * v1;
                }
                if (SPLIT_OUT) {
                    __nv_bfloat162 hh, ll;
                    hh.x = __float2bfloat16_rn(v0);
                    hh.y = __float2bfloat16_rn(v1);
                    ll.x = __float2bfloat16_rn(v0 - __bfloat162float(hh.x));
                    ll.y = __float2bfloat16_rn(v1 - __bfloat162float(hh.y));
                    *(uint32_t*)(o_hi + (size_t)row * 64 + col) = *(uint32_t*)&hh;
                    *(uint32_t*)(o_lo + (size_t)row * 64 + col) = *(uint32_t*)&ll;
                } else {
                    float2 v; v.x = v0; v.y = v1;
                    *(float2*)(o_f32 + (size_t)row * 64 + col) = v;
                }
            }
}

// ---------------------------------------------------------------------------
// Merged split: x | W1 | W2 | W3 -> bf16 hi/lo.  Also zeroes tap counters.
// ---------------------------------------------------------------------------
__global__ __launch_bounds__(256) void splitall_kernel(
    const float* __restrict__ x, __nv_bfloat16* __restrict__ xh, __nv_bfloat16* __restrict__ xl, int nx,
    const float* __restrict__ W1, __nv_bfloat16* __restrict__ h1, __nv_bfloat16* __restrict__ l1, int n1,
    const float* __restrict__ W2, __nv_bfloat16* __restrict__ h2, __nv_bfloat16* __restrict__ l2, int n2,
    const float* __restrict__ W3, __nv_bfloat16* __restrict__ h3, __nv_bfloat16* __restrict__ l3, int n3)
{
    if (blockIdx.x == 0 && threadIdx.x < KT1) g_tapcnt[threadIdx.x] = 0;
    const int total = nx + n1 + n2 + n3;
    for (int i = blockIdx.x * 256 + threadIdx.x; i < total; i += gridDim.x * 256) {
        const float* s; __nv_bfloat16 *hp, *lp; int j;
        if (i < nx)                { s = x;  hp = xh; lp = xl; j = i; }
        else if (i < nx + n1)      { s = W1; hp = h1; lp = l1; j = i - nx; }
        else if (i < nx + n1 + n2) { s = W2; hp = h2; lp = l2; j = i - nx - n1; }
        else                       { s = W3; hp = h3; lp = l3; j = i - nx - n1 - n2; }
        const float v = s[j];
        const __nv_bfloat16 h = __float2bfloat16_rn(v);
        hp[j] = h;
        lp[j] = __float2bfloat16_rn(v - __bfloat162float(h));
    }
}

__global__ __launch_bounds__(256) void bn_partial_kernel(
    const __nv_bfloat16* __restrict__ fh, const __nv_bfloat16* __restrict__ fl,
    int n2, float* __restrict__ partial)
{
    const int tid = threadIdx.x;
    const int c = tid & 63;
    const int sub = tid >> 6;
    float s = 0.f, s2 = 0.f;
    for (int r = blockIdx.x * 4 + sub; r < n2; r += gridDim.x * 4) {
        const size_t i = (size_t)r * 64 + c;
        const float v = __bfloat162float(fh[i]) + __bfloat162float(fl[i]);
        s += v; s2 += v * v;
    }
    __shared__ float sh[256], sh2[256];
    sh[tid] = s; sh2[tid] = s2;
    __syncthreads();
    if (tid < 64) {
        s  = sh[tid]  + sh[tid + 64]  + sh[tid + 128]  + sh[tid + 192];
        s2 = sh2[tid] + sh2[tid + 64] + sh2[tid + 128] + sh2[tid + 192];
        partial[blockIdx.x * 128 + tid]      = s;
        partial[blockIdx.x * 128 + 64 + tid] = s2;
    }
}

__global__ void bn_finalize_kernel(
    const float* __restrict__ partial, int G, int n2,
    const float* __restrict__ gamma, const float* __restrict__ beta,
    const float* __restrict__ scale, float* __restrict__ st)
{
    const int c = threadIdx.x;
    float s = 0.f, s2 = 0.f;
    for (int g = 0; g < G; ++g) {
        s  += partial[g * 128 + c];
        s2 += partial[g * 128 + 64 + c];
    }
    const float inv_n = 1.0f / (float)n2;
    const float mu  = s * inv_n;
    const float var = fmaxf(s2 * inv_n - mu * mu, 0.f);
    const float r   = rsqrtf(var + 1e-5f);
    const float sc  = scale[0];
    st[c]      = gamma[c] * r * sc;
    st[64 + c] = (beta[c] - mu * gamma[c] * r) * sc;
}

__global__ __launch_bounds__(256) void bn_apply_kernel(
    __nv_bfloat16* __restrict__ fh, __nv_bfloat16* __restrict__ fl,
    int n2, const float* __restrict__ st)
{
    const int i = blockIdx.x * 256 + threadIdx.x;
    if (i < n2 * 64) {
        const int c = i & 63;
        const float v = fmaf(__bfloat162float(fh[i]) + __bfloat162float(fl[i]),
                             st[c], st[64 + c]);
        const __nv_bfloat16 h = __float2bfloat16_rn(v);
        fh[i] = h;
        fl[i] = __float2bfloat16_rn(v - __bfloat162float(h));
    }
}

// ---------------------------------------------------------------------------
extern "C" void kernel_launch(void* const* d_in, const int* in_sizes, int n_in_arrs,
                              void* d_out, int out_size)
{
    const float* x     = (const float*)d_in[0];
    const float* W1    = (const float*)d_in[1];
    const float* b1    = (const float*)d_in[2];
    const float* W2    = (const float*)d_in[3];
    const float* b2    = (const float*)d_in[4];
    const float* W3    = (const float*)d_in[5];
    const float* b3    = (const float*)d_in[6];
    const float* gamma = (const float*)d_in[7];
    const float* beta  = (const float*)d_in[8];
    const float* scale = (const float*)d_in[9];
    const int* nmap1   = (const int*)d_in[10];
    const int* nmap2   = (const int*)d_in[11];
    const int* nmap3   = (const int*)d_in[12];

    const int N  = in_sizes[0] / 96;
    const int N2 = in_sizes[11] / 8;
    const int NB = (N + 255) / 256;

    __nv_bfloat16 *xh, *xl, *f1h, *f1l, *f2h, *f2l, *w1h, *w1l, *w2h, *w2l, *w3h, *w3l;
    float *partial, *st;
    cudaGetSymbolAddress((void**)&xh, g_x_hi);   cudaGetSymbolAddress((void**)&xl, g_x_lo);
    cudaGetSymbolAddress((void**)&f1h, g_f1_hi); cudaGetSymbolAddress((void**)&f1l, g_f1_lo);
    cudaGetSymbolAddress((void**)&f2h, g_f2_hi); cudaGetSymbolAddress((void**)&f2l, g_f2_lo);
    cudaGetSymbolAddress((void**)&w1h, g_w1_hi); cudaGetSymbolAddress((void**)&w1l, g_w1_lo);
    cudaGetSymbolAddress((void**)&w2h, g_w2_hi); cudaGetSymbolAddress((void**)&w2l, g_w2_lo);
    cudaGetSymbolAddress((void**)&w3h, g_w3_hi); cudaGetSymbolAddress((void**)&w3l, g_w3_lo);
    cudaGetSymbolAddress((void**)&partial, g_partial);
    cudaGetSymbolAddress((void**)&st, g_st);

    // prep: merged split (also zeroes tap counters)
    splitall_kernel<<<512, 256>>>(x, xh, xl, N * 96,
                                  W1, w1h, w1l, 27 * 96 * 64,
                                  W2, w2h, w2l, 8 * 64 * 64,
                                  W3, w3h, w3l, 27 * 64 * 64);

    // ---- conv1: compacted ----
    emit_fused<<<NB, 256>>>(nmap1, N, N);
    {
        constexpr int smem = (2 * 128 * 104 + 2 * 96 * 72) * 2;   // 80,896 B
        cudaFuncSetAttribute(conv1_compact,
                             cudaFuncAttributeMaxDynamicSharedMemorySize, smem);
        dim3 grid((N + 127) / 128, KT1);
        conv1_compact<<<grid, 256, smem>>>(xh, xl, w1h, w1l);
    }
    reduce1_kernel<<<(N + 7) / 8, 256>>>(b1, N, f1h, f1l);

    // ---- conv2: dense, 8 taps ----
    {
        constexpr int stage = (2 * 128 * 72 + 2 * 64 * 72) * 2;
        constexpr int smem  = 2 * stage;
        cudaFuncSetAttribute(sconv_mma<64, 8, true, true>,
                             cudaFuncAttributeMaxDynamicSharedMemorySize, smem);
        sconv_mma<64, 8, true, true><<<(N2 + 127) / 128, 256, smem>>>(
            f1h, f1l, N, nmap2, N2, w2h, w2l, b2, f2h, f2l, nullptr);
    }
    // ---- batch norm + scale ----
    {
        const int G = 120;
        bn_partial_kernel<<<G, 256>>>(f2h, f2l, N2, partial);
        bn_finalize_kernel<<<1, 64>>>(partial, G, N2, gamma, beta, scale, st);
        bn_apply_kernel<<<(N2 * 64 + 255) / 256, 256>>>(f2h, f2l, N2, st);
    }
    // ---- conv3: dense, 27 taps, fp32 out ----
    {
        constexpr int stage = (2 * 128 * 72 + 2 * 64 * 72) * 2;
        constexpr int smem  = 2 * stage;
        cudaFuncSetAttribute(sconv_mma<64, 27, false, false>,
                             cudaFuncAttributeMaxDynamicSharedMemorySize, smem);
        sconv_mma<64, 27, false, false><<<(N2 + 127) / 128, 256, smem>>>(
            f2h, f2l, N2, nmap3, N2, w3h, w3l, b3, nullptr, nullptr, (float*)d_out);
    }
}

// round 10
// speedup vs baseline: 1.2164x; 1.0060x over previous
#include <cuda_runtime.h>
#include <cuda_bf16.h>
#include <cstdint>

// ===========================================================================
// Sparse conv encoder, mma.sync bf16 hi/lo x3.
// conv1: per-tap COMPACTED gather-GEMM, fused atomic-emit prep,
//        write-scatter/read-stream contrib layout (R10);
// conv2/conv3: dense cp.async double-buffered tap pipeline.
// ===========================================================================

#define MAXN 60032
#define KT1 27

__device__ __nv_bfloat16 g_x_hi[MAXN * 96];
__device__ __nv_bfloat16 g_x_lo[MAXN * 96];
__device__ __nv_bfloat16 g_f1_hi[MAXN * 64];
__device__ __nv_bfloat16 g_f1_lo[MAXN * 64];
__device__ __nv_bfloat16 g_f2_hi[MAXN * 64];
__device__ __nv_bfloat16 g_f2_lo[MAXN * 64];
__device__ __nv_bfloat16 g_w1_hi[27 * 96 * 64];
__device__ __nv_bfloat16 g_w1_lo[27 * 96 * 64];
__device__ __nv_bfloat16 g_w2_hi[8 * 64 * 64];
__device__ __nv_bfloat16 g_w2_lo[8 * 64 * 64];
__device__ __nv_bfloat16 g_w3_hi[27 * 64 * 64];
__device__ __nv_bfloat16 g_w3_lo[27 * 64 * 64];
__device__ float g_partial[128 * 128];
__device__ float g_st[128];

// conv1 compaction (fixed-stride per-tap regions: tap k owns [k*MAXN, ...))
__device__ int   g_mask[MAXN];
__device__ int   g_tapcnt[KT1];
__device__ int   g_pairidx[KT1 * MAXN];          // gather source row
__device__ int   g_pairdst[KT1 * MAXN];          // (row<<5)|j  dest slot
__device__ float g_contrib[(size_t)MAXN * 32 * 64];   // [row][j][64]

__device__ __forceinline__ uint32_t smem_u32(const void* p) {
    uint32_t a;
    asm("{ .reg .u64 t; cvta.to.shared.u64 t, %1; cvt.u32.u64 %0, t; }"
        : "=r"(a) : "l"(p));
    return a;
}
__device__ __forceinline__ void cp16(uint32_t s, const void* g, int sz) {
    asm volatile("cp.async.cg.shared.global [%0], [%1], 16, %2;"
                 :: "r"(s), "l"(g), "r"(sz) : "memory");
}
__device__ __forceinline__ void cp_commit() {
    asm volatile("cp.async.commit_group;" ::: "memory");
}
template <int N>
__device__ __forceinline__ void cp_wait() {
    asm volatile("cp.async.wait_group %0;" :: "n"(N) : "memory");
}
__device__ __forceinline__ void ldsm_x4(uint32_t* r, uint32_t addr) {
    asm volatile("ldmatrix.sync.aligned.m8n8.x4.shared.b16 {%0,%1,%2,%3}, [%4];"
                 : "=r"(r[0]), "=r"(r[1]), "=r"(r[2]), "=r"(r[3]) : "r"(addr));
}
__device__ __forceinline__ void ldsm_x4_t(uint32_t* r, uint32_t addr) {
    asm volatile("ldmatrix.sync.aligned.m8n8.x4.trans.shared.b16 {%0,%1,%2,%3}, [%4];"
                 : "=r"(r[0]), "=r"(r[1]), "=r"(r[2]), "=r"(r[3]) : "r"(addr));
}
__device__ __forceinline__ void mma_bf16(float* d, const uint32_t* a, const uint32_t* b) {
    asm volatile(
        "mma.sync.aligned.m16n8k16.row.col.f32.bf16.bf16.f32 "
        "{%0,%1,%2,%3}, {%4,%5,%6,%7}, {%8,%9}, {%0,%1,%2,%3};"
        : "+f"(d[0]), "+f"(d[1]), "+f"(d[2]), "+f"(d[3])
        : "r"(a[0]), "r"(a[1]), "r"(a[2]), "r"(a[3]), "r"(b[0]), "r"(b[1]));
}

// ===========================================================================
// Fused compaction: mask + per-block histogram + atomic block-base + emit.
// Pair placement order varies with block arrival, but each contribution's
// DEST slot (row, j ascending-tap) is fixed, so the reduction order and the
// final output are replay-deterministic.
// ===========================================================================
__global__ __launch_bounds__(256) void emit_fused(
    const int* __restrict__ nmap, int n, int n_in)
{
    const int t = threadIdx.x, lane = t & 31, w = t >> 5;
    const int row = blockIdx.x * 256 + t;

    int idxs[KT1];
    unsigned m = 0;
    if (row < n) {
        #pragma unroll
        for (int k = 0; k < KT1; ++k) {
            idxs[k] = __ldg(&nmap[(size_t)row * KT1 + k]);
            if (idxs[k] < n_in) m |= 1u << k;
        }
        g_mask[row] = (int)m;
    }

    __shared__ int hist[KT1], base[KT1], wt[KT1][8];
    if (t < KT1) hist[t] = 0;
    __syncthreads();
    #pragma unroll
    for (int k = 0; k < KT1; ++k) {
        const unsigned bal = __ballot_sync(0xffffffffu, (m >> k) & 1);
        if (lane == 0) { wt[k][w] = __popc(bal); if (bal) atomicAdd(&hist[k], __popc(bal)); }
    }
    __syncthreads();
    if (t < KT1) base[t] = atomicAdd(&g_tapcnt[t], hist[t]);
    __syncthreads();

    int j = 0;
    #pragma unroll
    for (int k = 0; k < KT1; ++k) {
        const int valid = (m >> k) & 1;
        const unsigned bal = __ballot_sync(0xffffffffu, valid);
        if (valid) {
            int wb = 0;
            #pragma unroll
            for (int i = 0; i < 8; ++i) if (i < w) wb += wt[k][i];
            const int rank = wb + __popc(bal & ((1u << lane) - 1u));
            const int pos  = k * MAXN + base[k] + rank;
            g_pairidx[pos] = idxs[k];
            g_pairdst[pos] = (row << 5) | j;
            ++j;
        }
    }
}

// ===========================================================================
// conv1 compact GEMM: one tap per CTA.y, 128 compacted rows x 64 cols,
// 8 warps (4x2), warp tile 32x32.  Epilogue scatters to [row][j][64].
// ===========================================================================
__global__ __launch_bounds__(256) void conv1_compact(
    const __nv_bfloat16* __restrict__ a_hi, const __nv_bfloat16* __restrict__ a_lo,
    const __nv_bfloat16* __restrict__ w_hi, const __nv_bfloat16* __restrict__ w_lo)
{
    constexpr int CIN = 96;
    constexpr int LDA = CIN + 8;
    constexpr int LDB = 72;
    constexpr int KSTEPS = CIN / 16;
    constexpr int CPR = CIN / 8;
    constexpr int A_HALVES = 128 * LDA;
    constexpr int B_HALVES = CIN * LDB;
    constexpr uint32_t OFF_ALO = (uint32_t)A_HALVES * 2;
    constexpr uint32_t OFF_BHI = (uint32_t)(2 * A_HALVES) * 2;
    constexpr uint32_t OFF_BLO = (uint32_t)(2 * A_HALVES + B_HALVES) * 2;

    const int k = blockIdx.y;
    const int tot = g_tapcnt[k];
    const int tilestart = blockIdx.x * 128;
    if (tilestart >= tot) return;
    const int q0 = k * MAXN + tilestart;

    extern __shared__ __align__(16) __nv_bfloat16 smem[];
    const uint32_t sb = smem_u32(smem);
    const int tid = threadIdx.x, wid = tid >> 5, lane = tid & 31;
    const int wm = (wid >> 1) * 32, wn = (wid & 1) * 32;
    const int lrow = lane & 15, lcol8 = (lane >> 4) * 8;

    #pragma unroll 2
    for (int i = tid; i < 2 * 128 * CPR; i += 256) {
        const int buf = i / (128 * CPR);
        const int j   = i % (128 * CPR);
        const int r   = j / CPR, c = j % CPR;
        const int ok  = tilestart + r < tot;
        const int idx = ok ? __ldg(&g_pairidx[q0 + r]) : 0;
        const __nv_bfloat16* src = (buf ? a_lo : a_hi) + (size_t)idx * CIN + c * 8;
        cp16(sb + (buf ? OFF_ALO : 0u) + (uint32_t)(r * LDA + c * 8) * 2,
             src, ok ? 16 : 0);
    }
    #pragma unroll 2
    for (int i = tid; i < 2 * CIN * 8; i += 256) {
        const int buf = i / (CIN * 8);
        const int j   = i % (CIN * 8);
        const int r   = j >> 3, c = j & 7;
        const __nv_bfloat16* src = (buf ? w_lo : w_hi)
            + (size_t)k * CIN * 64 + r * 64 + c * 8;
        cp16(sb + (buf ? OFF_BLO : OFF_BHI) + (uint32_t)(r * LDB + c * 8) * 2,
             src, 16);
    }
    cp_commit();
    cp_wait<0>();
    __syncthreads();

    float acc[2][4][4] = {};
    #pragma unroll
    for (int s = 0; s < KSTEPS; ++s) {
        uint32_t ah[2][4], al[2][4];
        #pragma unroll
        for (int mt = 0; mt < 2; ++mt) {
            const uint32_t off = (uint32_t)((wm + mt * 16 + lrow) * LDA
                                            + s * 16 + lcol8) * 2;
            ldsm_x4(ah[mt], sb + off);
            ldsm_x4(al[mt], sb + OFF_ALO + off);
        }
        uint32_t bh[2][4], bl[2][4];
        #pragma unroll
        for (int p = 0; p < 2; ++p) {
            const uint32_t off = (uint32_t)((s * 16 + lrow) * LDB
                                            + wn + p * 16 + lcol8) * 2;
            ldsm_x4_t(bh[p], sb + OFF_BHI + off);
            ldsm_x4_t(bl[p], sb + OFF_BLO + off);
        }
        #pragma unroll
        for (int mt = 0; mt < 2; ++mt)
            #pragma unroll
            for (int nt = 0; nt < 4; ++nt) {
                const uint32_t* Bh = &bh[nt >> 1][(nt & 1) * 2];
                const uint32_t* Bl = &bl[nt >> 1][(nt & 1) * 2];
                mma_bf16(acc[mt][nt], ah[mt], Bh);
                mma_bf16(acc[mt][nt], ah[mt], Bl);
                mma_bf16(acc[mt][nt], al[mt], Bh);
            }
    }

    // scatter contributions to their per-row slots
    #pragma unroll
    for (int mt = 0; mt < 2; ++mt)
        #pragma unroll
        for (int h = 0; h < 2; ++h) {
            const int rl = wm + mt * 16 + h * 8 + (lane >> 2);
            if (tilestart + rl >= tot) continue;
            const int dst = __ldg(&g_pairdst[q0 + rl]);
            float* out = g_contrib + (size_t)dst * 64;
            #pragma unroll
            for (int nt = 0; nt < 4; ++nt) {
                const int col = wn + nt * 8 + (lane & 3) * 2;
                float2 v;
                v.x = acc[mt][nt][h * 2];
                v.y = acc[mt][nt][h * 2 + 1];
                *(float2*)(out + col) = v;
            }
        }
}

// reduce per-row contributions (contiguous, ascending-tap order) -> f1
__global__ __launch_bounds__(256) void reduce1_kernel(
    const float* __restrict__ bias, int n,
    __nv_bfloat16* __restrict__ o_hi, __nv_bfloat16* __restrict__ o_lo)
{
    const int row = blockIdx.x * 8 + (threadIdx.x >> 5);
    if (row >= n) return;
    const int lane = threadIdx.x & 31;
    const int cnt  = __popc((unsigned)g_mask[row]);
    const int c0   = lane * 2;
    const float* src = g_contrib + ((size_t)row << 5) * 64 + c0;
    float s0 = __ldg(&bias[c0]), s1 = __ldg(&bias[c0 + 1]);
    for (int j = 0; j < cnt; ++j) {
        const float2 v = *(const float2*)(src + (size_t)j * 64);
        s0 += v.x; s1 += v.y;
    }
    s0 = s0 >= 0.f ? s0 : 0.1f * s0;
    s1 = s1 >= 0.f ? s1 : 0.1f * s1;
    __nv_bfloat162 hh, ll;
    hh.x = __float2bfloat16_rn(s0);
    hh.y = __float2bfloat16_rn(s1);
    ll.x = __float2bfloat16_rn(s0 - __bfloat162float(hh.x));
    ll.y = __float2bfloat16_rn(s1 - __bfloat162float(hh.y));
    *(uint32_t*)(o_hi + (size_t)row * 64 + c0) = *(uint32_t*)&hh;
    *(uint32_t*)(o_lo + (size_t)row * 64 + c0) = *(uint32_t*)&ll;
}

// ===========================================================================
// Dense gather-GEMM (conv2/conv3): 2-stage cp.async pipeline, 8 warps (4x2)
// ===========================================================================
template <int CIN, int KT, bool LEAKY, bool SPLIT_OUT>
__global__ __launch_bounds__(256) void sconv_mma(
    const __nv_bfloat16* __restrict__ a_hi, const __nv_bfloat16* __restrict__ a_lo,
    int n_in, const int* __restrict__ nmap, int n_out,
    const __nv_bfloat16* __restrict__ w_hi, const __nv_bfloat16* __restrict__ w_lo,
    const float* __restrict__ bias,
    __nv_bfloat16* __restrict__ o_hi, __nv_bfloat16* __restrict__ o_lo,
    float* __restrict__ o_f32)
{
    constexpr int LDA = CIN + 8;
    constexpr int LDB = 72;
    constexpr int KSTEPS = CIN / 16;
    constexpr int CPR = CIN / 8;
    constexpr int A_HALVES = 128 * LDA;
    constexpr int B_HALVES = CIN * LDB;
    constexpr uint32_t OFF_ALO = (uint32_t)A_HALVES * 2;
    constexpr uint32_t OFF_BHI = (uint32_t)(2 * A_HALVES) * 2;
    constexpr uint32_t OFF_BLO = (uint32_t)(2 * A_HALVES + B_HALVES) * 2;
    constexpr uint32_t STAGE   = (uint32_t)(2 * A_HALVES + 2 * B_HALVES) * 2;

    extern __shared__ __align__(16) __nv_bfloat16 smem[];
    const uint32_t sb = smem_u32(smem);

    const int tid  = threadIdx.x;
    const int wid  = tid >> 5;
    const int lane = tid & 31;
    const int row0 = blockIdx.x * 128;
    const int wm   = (wid >> 1) * 32;
    const int wn   = (wid & 1) * 32;
    const int lrow = lane & 15, lcol8 = (lane >> 4) * 8;

    float acc[2][4][4] = {};

    auto prefetch = [&](int t, uint32_t stoff) {
        #pragma unroll 2
        for (int i = tid; i < 2 * 128 * CPR; i += 256) {
            const int buf = i / (128 * CPR);
            const int j   = i % (128 * CPR);
            const int r   = j / CPR, c = j % CPR;
            const int rr  = row0 + r;
            int idx = n_in;
            if (rr < n_out) idx = __ldg(&nmap[(size_t)rr * KT + t]);
            const int ok = idx < n_in;
            const __nv_bfloat16* src = (buf ? a_lo : a_hi)
                + (size_t)(ok ? idx : 0) * CIN + c * 8;
            cp16(sb + stoff + (buf ? OFF_ALO : 0u)
                 + (uint32_t)(r * LDA + c * 8) * 2, src, ok ? 16 : 0);
        }
        #pragma unroll 2
        for (int i = tid; i < 2 * CIN * 8; i += 256) {
            const int buf = i / (CIN * 8);
            const int j   = i % (CIN * 8);
            const int r   = j >> 3, c = j & 7;
            const __nv_bfloat16* src = (buf ? w_lo : w_hi)
                + (size_t)t * CIN * 64 + r * 64 + c * 8;
            cp16(sb + stoff + (buf ? OFF_BLO : OFF_BHI)
                 + (uint32_t)(r * LDB + c * 8) * 2, src, 16);
        }
    };

    prefetch(0, 0);
    cp_commit();

    for (int t = 0; t < KT; ++t) {
        const uint32_t stoff = (t & 1) ? STAGE : 0u;
        if (t + 1 < KT) {
            prefetch(t + 1, (t & 1) ? 0u : STAGE);
            cp_commit();
            cp_wait<1>();
        } else {
            cp_wait<0>();
        }
        __syncthreads();

        #pragma unroll
        for (int s = 0; s < KSTEPS; ++s) {
            uint32_t ah[2][4], al[2][4];
            #pragma unroll
            for (int mt = 0; mt < 2; ++mt) {
                const uint32_t off = (uint32_t)((wm + mt * 16 + lrow) * LDA
                                                + s * 16 + lcol8) * 2;
                ldsm_x4(ah[mt], sb + stoff + off);
                ldsm_x4(al[mt], sb + stoff + OFF_ALO + off);
            }
            uint32_t bh[2][4], bl[2][4];
            #pragma unroll
            for (int p = 0; p < 2; ++p) {
                const uint32_t off = (uint32_t)((s * 16 + lrow) * LDB
                                                + wn + p * 16 + lcol8) * 2;
                ldsm_x4_t(bh[p], sb + stoff + OFF_BHI + off);
                ldsm_x4_t(bl[p], sb + stoff + OFF_BLO + off);
            }
            #pragma unroll
            for (int mt = 0; mt < 2; ++mt)
                #pragma unroll
                for (int nt = 0; nt < 4; ++nt) {
                    const uint32_t* Bh = &bh[nt >> 1][(nt & 1) * 2];
                    const uint32_t* Bl = &bl[nt >> 1][(nt & 1) * 2];
                    mma_bf16(acc[mt][nt], ah[mt], Bh);
                    mma_bf16(acc[mt][nt], ah[mt], Bl);
                    mma_bf16(acc[mt][nt], al[mt], Bh);
                }
        }
        __syncthreads();
    }

    #pragma unroll
    for (int mt = 0; mt < 2; ++mt)
        #pragma unroll
        for (int nt = 0; nt < 4; ++nt)
            #pragma unroll
            for (int h = 0; h < 2; ++h) {
                const int row = row0 + wm + mt * 16 + h * 8 + (lane >> 2);
                if (row >= n_out) continue;
                const int col = wn + nt * 8 + (lane & 3) * 2;
                float v0 = acc[mt][nt][h * 2]     + __ldg(&bias[col]);
                float v1 = acc[mt][nt][h * 2 + 1] + __ldg(&bias[col + 1]);
                if (LEAKY) {
                    v0 = v0 >= 0.f ? v0 : 0.1f * v0;
                    v1 = v1 >= 0.f ? v1 : 0.1f * v1;
                }
                if (SPLIT_OUT) {
                    __nv_bfloat162 hh, ll;
                    hh.x = __float2bfloat16_rn(v0);
                    hh.y = __float2bfloat16_rn(v1);
                    ll.x = __float2bfloat16_rn(v0 - __bfloat162float(hh.x));
                    ll.y = __float2bfloat16_rn(v1 - __bfloat162float(hh.y));
                    *(uint32_t*)(o_hi + (size_t)row * 64 + col) = *(uint32_t*)&hh;
                    *(uint32_t*)(o_lo + (size_t)row * 64 + col) = *(uint32_t*)&ll;
                } else {
                    float2 v; v.x = v0; v.y = v1;
                    *(float2*)(o_f32 + (size_t)row * 64 + col) = v;
                }
            }
}

// ---------------------------------------------------------------------------
// Merged split: x | W1 | W2 | W3 -> bf16 hi/lo.  Also zeroes tap counters.
// ---------------------------------------------------------------------------
__global__ __launch_bounds__(256) void splitall_kernel(
    const float* __restrict__ x, __nv_bfloat16* __restrict__ xh, __nv_bfloat16* __restrict__ xl, int nx,
    const float* __restrict__ W1, __nv_bfloat16* __restrict__ h1, __nv_bfloat16* __restrict__ l1, int n1,
    const float* __restrict__ W2, __nv_bfloat16* __restrict__ h2, __nv_bfloat16* __restrict__ l2, int n2,
    const float* __restrict__ W3, __nv_bfloat16* __restrict__ h3, __nv_bfloat16* __restrict__ l3, int n3)
{
    if (blockIdx.x == 0 && threadIdx.x < KT1) g_tapcnt[threadIdx.x] = 0;
    const int total = nx + n1 + n2 + n3;
    for (int i = blockIdx.x * 256 + threadIdx.x; i < total; i += gridDim.x * 256) {
        const float* s; __nv_bfloat16 *hp, *lp; int j;
        if (i < nx)                { s = x;  hp = xh; lp = xl; j = i; }
        else if (i < nx + n1)      { s = W1; hp = h1; lp = l1; j = i - nx; }
        else if (i < nx + n1 + n2) { s = W2; hp = h2; lp = l2; j = i - nx - n1; }
        else                       { s = W3; hp = h3; lp = l3; j = i - nx - n1 - n2; }
        const float v = s[j];
        const __nv_bfloat16 h = __float2bfloat16_rn(v);
        hp[j] = h;
        lp[j] = __float2bfloat16_rn(v - __bfloat162float(h));
    }
}

__global__ __launch_bounds__(256) void bn_partial_kernel(
    const __nv_bfloat16* __restrict__ fh, const __nv_bfloat16* __restrict__ fl,
    int n2, float* __restrict__ partial)
{
    const int tid = threadIdx.x;
    const int c = tid & 63;
    const int sub = tid >> 6;
    float s = 0.f, s2 = 0.f;
    for (int r = blockIdx.x * 4 + sub; r < n2; r += gridDim.x * 4) {
        const size_t i = (size_t)r * 64 + c;
        const float v = __bfloat162float(fh[i]) + __bfloat162float(fl[i]);
        s += v; s2 += v * v;
    }
    __shared__ float sh[256], sh2[256];
    sh[tid] = s; sh2[tid] = s2;
    __syncthreads();
    if (tid < 64) {
        s  = sh[tid]  + sh[tid + 64]  + sh[tid + 128]  + sh[tid + 192];
        s2 = sh2[tid] + sh2[tid + 64] + sh2[tid + 128] + sh2[tid + 192];
        partial[blockIdx.x * 128 + tid]      = s;
        partial[blockIdx.x * 128 + 64 + tid] = s2;
    }
}

__global__ void bn_finalize_kernel(
    const float* __restrict__ partial, int G, int n2,
    const float* __restrict__ gamma, const float* __restrict__ beta,
    const float* __restrict__ scale, float* __restrict__ st)
{
    const int c = threadIdx.x;
    float s = 0.f, s2 = 0.f;
    for (int g = 0; g < G; ++g) {
        s  += partial[g * 128 + c];
        s2 += partial[g * 128 + 64 + c];
    }
    const float inv_n = 1.0f / (float)n2;
    const float mu  = s * inv_n;
    const float var = fmaxf(s2 * inv_n - mu * mu, 0.f);
    const float r   = rsqrtf(var + 1e-5f);
    const float sc  = scale[0];
    st[c]      = gamma[c] * r * sc;
    st[64 + c] = (beta[c] - mu * gamma[c] * r) * sc;
}

__global__ __launch_bounds__(256) void bn_apply_kernel(
    __nv_bfloat16* __restrict__ fh, __nv_bfloat16* __restrict__ fl,
    int n2, const float* __restrict__ st)
{
    const int i = blockIdx.x * 256 + threadIdx.x;
    if (i < n2 * 64) {
        const int c = i & 63;
        const float v = fmaf(__bfloat162float(fh[i]) + __bfloat162float(fl[i]),
                             st[c], st[64 + c]);
        const __nv_bfloat16 h = __float2bfloat16_rn(v);
        fh[i] = h;
        fl[i] = __float2bfloat16_rn(v - __bfloat162float(h));
    }
}

// ---------------------------------------------------------------------------
extern "C" void kernel_launch(void* const* d_in, const int* in_sizes, int n_in_arrs,
                              void* d_out, int out_size)
{
    const float* x     = (const float*)d_in[0];
    const float* W1    = (const float*)d_in[1];
    const float* b1    = (const float*)d_in[2];
    const float* W2    = (const float*)d_in[3];
    const float* b2    = (const float*)d_in[4];
    const float* W3    = (const float*)d_in[5];
    const float* b3    = (const float*)d_in[6];
    const float* gamma = (const float*)d_in[7];
    const float* beta  = (const float*)d_in[8];
    const float* scale = (const float*)d_in[9];
    const int* nmap1   = (const int*)d_in[10];
    const int* nmap2   = (const int*)d_in[11];
    const int* nmap3   = (const int*)d_in[12];

    const int N  = in_sizes[0] / 96;
    const int N2 = in_sizes[11] / 8;
    const int NB = (N + 255) / 256;

    __nv_bfloat16 *xh, *xl, *f1h, *f1l, *f2h, *f2l, *w1h, *w1l, *w2h, *w2l, *w3h, *w3l;
    float *partial, *st;
    cudaGetSymbolAddress((void**)&xh, g_x_hi);   cudaGetSymbolAddress((void**)&xl, g_x_lo);
    cudaGetSymbolAddress((void**)&f1h, g_f1_hi); cudaGetSymbolAddress((void**)&f1l, g_f1_lo);
    cudaGetSymbolAddress((void**)&f2h, g_f2_hi); cudaGetSymbolAddress((void**)&f2l, g_f2_lo);
    cudaGetSymbolAddress((void**)&w1h, g_w1_hi); cudaGetSymbolAddress((void**)&w1l, g_w1_lo);
    cudaGetSymbolAddress((void**)&w2h, g_w2_hi); cudaGetSymbolAddress((void**)&w2l, g_w2_lo);
    cudaGetSymbolAddress((void**)&w3h, g_w3_hi); cudaGetSymbolAddress((void**)&w3l, g_w3_lo);
    cudaGetSymbolAddress((void**)&partial, g_partial);
    cudaGetSymbolAddress((void**)&st, g_st);

    // prep: merged split (also zeroes tap counters)
    splitall_kernel<<<512, 256>>>(x, xh, xl, N * 96,
                                  W1, w1h, w1l, 27 * 96 * 64,
                                  W2, w2h, w2l, 8 * 64 * 64,
                                  W3, w3h, w3l, 27 * 64 * 64);

    // ---- conv1: compacted ----
    emit_fused<<<NB, 256>>>(nmap1, N, N);
    {
        constexpr int smem = (2 * 128 * 104 + 2 * 96 * 72) * 2;   // 80,896 B
        cudaFuncSetAttribute(conv1_compact,
                             cudaFuncAttributeMaxDynamicSharedMemorySize, smem);
        dim3 grid((N + 127) / 128, KT1);
        conv1_compact<<<grid, 256, smem>>>(xh, xl, w1h, w1l);
    }
    reduce1_kernel<<<(N + 7) / 8, 256>>>(b1, N, f1h, f1l);

    // ---- conv2: dense, 8 taps ----
    {
        constexpr int stage = (2 * 128 * 72 + 2 * 64 * 72) * 2;
        constexpr int smem  = 2 * stage;
        cudaFuncSetAttribute(sconv_mma<64, 8, true, true>,
                             cudaFuncAttributeMaxDynamicSharedMemorySize, smem);
        sconv_mma<64, 8, true, true><<<(N2 + 127) / 128, 256, smem>>>(
            f1h, f1l, N, nmap2, N2, w2h, w2l, b2, f2h, f2l, nullptr);
    }
    // ---- batch norm + scale ----
    {
        const int G = 120;
        bn_partial_kernel<<<G, 256>>>(f2h, f2l, N2, partial);
        bn_finalize_kernel<<<1, 64>>>(partial, G, N2, gamma, beta, scale, st);
        bn_apply_kernel<<<(N2 * 64 + 255) / 256, 256>>>(f2h, f2l, N2, st);
    }
    // ---- conv3: dense, 27 taps, fp32 out ----
    {
        constexpr int stage = (2 * 128 * 72 + 2 * 64 * 72) * 2;
        constexpr int smem  = 2 * stage;
        cudaFuncSetAttribute(sconv_mma<64, 27, false, false>,
                             cudaFuncAttributeMaxDynamicSharedMemorySize, smem);
        sconv_mma<64, 27, false, false><<<(N2 + 127) / 128, 256, smem>>>(
            f2h, f2l, N2, nmap3, N2, w3h, w3l, b3, nullptr, nullptr, (float*)d_out);
    }
}

// round 11
// speedup vs baseline: 1.2524x; 1.0296x over previous
#include <cuda_runtime.h>
#include <cuda_bf16.h>
#include <cstdint>

// ===========================================================================
// Sparse conv encoder, mma.sync bf16 hi/lo x3.
// conv1 AND conv2: per-tap COMPACTED gather-GEMM (fused atomic-emit prep,
//   write-scatter/read-stream contrib); conv3: dense cp.async pipeline.
// All GEMMs: 256 threads, 8 warps (4x2), warp tile 32x32 (proven config).
// ===========================================================================

#define MAXN 60032
#define KT1 27
#define KT2 8

__device__ __nv_bfloat16 g_x_hi[MAXN * 96];
__device__ __nv_bfloat16 g_x_lo[MAXN * 96];
__device__ __nv_bfloat16 g_f1_hi[MAXN * 64];
__device__ __nv_bfloat16 g_f1_lo[MAXN * 64];
__device__ __nv_bfloat16 g_f2_hi[MAXN * 64];
__device__ __nv_bfloat16 g_f2_lo[MAXN * 64];
__device__ __nv_bfloat16 g_w1_hi[27 * 96 * 64];
__device__ __nv_bfloat16 g_w1_lo[27 * 96 * 64];
__device__ __nv_bfloat16 g_w2_hi[8 * 64 * 64];
__device__ __nv_bfloat16 g_w2_lo[8 * 64 * 64];
__device__ __nv_bfloat16 g_w3_hi[27 * 64 * 64];
__device__ __nv_bfloat16 g_w3_lo[27 * 64 * 64];
__device__ float g_partial[128 * 128];
__device__ float g_st[128];

// compaction structures
__device__ int   g_mask1[MAXN];
__device__ int   g_mask2[MAXN];
__device__ int   g_tapcnt1[KT1];
__device__ int   g_tapcnt2[KT2];
__device__ int   g_pairidx1[KT1 * MAXN];
__device__ int   g_pairdst1[KT1 * MAXN];         // (row<<5)|j
__device__ int   g_pairidx2[KT2 * MAXN];
__device__ int   g_pairdst2[KT2 * MAXN];         // (row<<3)|j
__device__ float g_contrib[(size_t)MAXN * 32 * 64];

__device__ __forceinline__ uint32_t smem_u32(const void* p) {
    uint32_t a;
    asm("{ .reg .u64 t; cvta.to.shared.u64 t, %1; cvt.u32.u64 %0, t; }"
        : "=r"(a) : "l"(p));
    return a;
}
__device__ __forceinline__ void cp16(uint32_t s, const void* g, int sz) {
    asm volatile("cp.async.cg.shared.global [%0], [%1], 16, %2;"
                 :: "r"(s), "l"(g), "r"(sz) : "memory");
}
__device__ __forceinline__ void cp_commit() {
    asm volatile("cp.async.commit_group;" ::: "memory");
}
template <int N>
__device__ __forceinline__ void cp_wait() {
    asm volatile("cp.async.wait_group %0;" :: "n"(N) : "memory");
}
__device__ __forceinline__ void ldsm_x4(uint32_t* r, uint32_t addr) {
    asm volatile("ldmatrix.sync.aligned.m8n8.x4.shared.b16 {%0,%1,%2,%3}, [%4];"
                 : "=r"(r[0]), "=r"(r[1]), "=r"(r[2]), "=r"(r[3]) : "r"(addr));
}
__device__ __forceinline__ void ldsm_x4_t(uint32_t* r, uint32_t addr) {
    asm volatile("ldmatrix.sync.aligned.m8n8.x4.trans.shared.b16 {%0,%1,%2,%3}, [%4];"
                 : "=r"(r[0]), "=r"(r[1]), "=r"(r[2]), "=r"(r[3]) : "r"(addr));
}
__device__ __forceinline__ void mma_bf16(float* d, const uint32_t* a, const uint32_t* b) {
    asm volatile(
        "mma.sync.aligned.m16n8k16.row.col.f32.bf16.bf16.f32 "
        "{%0,%1,%2,%3}, {%4,%5,%6,%7}, {%8,%9}, {%0,%1,%2,%3};"
        : "+f"(d[0]), "+f"(d[1]), "+f"(d[2]), "+f"(d[3])
        : "r"(a[0]), "r"(a[1]), "r"(a[2]), "r"(a[3]), "r"(b[0]), "r"(b[1]));
}

// ===========================================================================
// Fused compaction (templated): mask + block histogram + atomic base + emit.
// Dest slot (row<<SHIFT)|j fixed by row & ascending-tap rank j ->
// reduction order and output replay-deterministic.
// ===========================================================================
template <int KT, int SHIFT>
__global__ __launch_bounds__(256) void emit_fused(
    const int* __restrict__ nmap, int n, int n_in,
    int* __restrict__ maskp, int* __restrict__ tapcnt,
    int* __restrict__ pairidx, int* __restrict__ pairdst)
{
    const int t = threadIdx.x, lane = t & 31, w = t >> 5;
    const int row = blockIdx.x * 256 + t;

    int idxs[KT];
    unsigned m = 0;
    if (row < n) {
        #pragma unroll
        for (int k = 0; k < KT; ++k) {
            idxs[k] = __ldg(&nmap[(size_t)row * KT + k]);
            if (idxs[k] < n_in) m |= 1u << k;
        }
        maskp[row] = (int)m;
    }

    __shared__ int hist[KT], base[KT], wt[KT][8];
    if (t < KT) hist[t] = 0;
    __syncthreads();
    #pragma unroll
    for (int k = 0; k < KT; ++k) {
        const unsigned bal = __ballot_sync(0xffffffffu, (m >> k) & 1);
        if (lane == 0) { wt[k][w] = __popc(bal); if (bal) atomicAdd(&hist[k], __popc(bal)); }
    }
    __syncthreads();
    if (t < KT) base[t] = atomicAdd(&tapcnt[t], hist[t]);
    __syncthreads();

    int j = 0;
    #pragma unroll
    for (int k = 0; k < KT; ++k) {
        const int valid = (m >> k) & 1;
        const unsigned bal = __ballot_sync(0xffffffffu, valid);
        if (valid) {
            int wb = 0;
            #pragma unroll
            for (int i = 0; i < 8; ++i) if (i < w) wb += wt[k][i];
            const int rank = wb + __popc(bal & ((1u << lane) - 1u));
            const int pos  = k * MAXN + base[k] + rank;
            pairidx[pos] = idxs[k];
            pairdst[pos] = (row << SHIFT) | j;
            ++j;
        }
    }
}

// ===========================================================================
// Compact GEMM: one tap per CTA.y, 128 compacted rows x 64 cols,
// 8 warps (4x2), warp tile 32x32.  Epilogue scatters to contrib[dst][64].
// ===========================================================================
template <int CIN>
__global__ __launch_bounds__(256) void conv_compact(
    const __nv_bfloat16* __restrict__ a_hi, const __nv_bfloat16* __restrict__ a_lo,
    const __nv_bfloat16* __restrict__ w_hi, const __nv_bfloat16* __restrict__ w_lo,
    const int* __restrict__ tapcnt,
    const int* __restrict__ pairidx, const int* __restrict__ pairdst)
{
    constexpr int LDA = CIN + 8;
    constexpr int LDB = 72;
    constexpr int KSTEPS = CIN / 16;
    constexpr int CPR = CIN / 8;
    constexpr int A_HALVES = 128 * LDA;
    constexpr int B_HALVES = CIN * LDB;
    constexpr uint32_t OFF_ALO = (uint32_t)A_HALVES * 2;
    constexpr uint32_t OFF_BHI = (uint32_t)(2 * A_HALVES) * 2;
    constexpr uint32_t OFF_BLO = (uint32_t)(2 * A_HALVES + B_HALVES) * 2;

    const int k = blockIdx.y;
    const int tot = __ldg(&tapcnt[k]);
    const int tilestart = blockIdx.x * 128;
    if (tilestart >= tot) return;
    const int q0 = k * MAXN + tilestart;

    extern __shared__ __align__(16) __nv_bfloat16 smem[];
    const uint32_t sb = smem_u32(smem);
    const int tid = threadIdx.x, wid = tid >> 5, lane = tid & 31;
    const int wm = (wid >> 1) * 32, wn = (wid & 1) * 32;
    const int lrow = lane & 15, lcol8 = (lane >> 4) * 8;

    #pragma unroll 2
    for (int i = tid; i < 2 * 128 * CPR; i += 256) {
        const int buf = i / (128 * CPR);
        const int j   = i % (128 * CPR);
        const int r   = j / CPR, c = j % CPR;
        const int ok  = tilestart + r < tot;
        const int idx = ok ? __ldg(&pairidx[q0 + r]) : 0;
        const __nv_bfloat16* src = (buf ? a_lo : a_hi) + (size_t)idx * CIN + c * 8;
        cp16(sb + (buf ? OFF_ALO : 0u) + (uint32_t)(r * LDA + c * 8) * 2,
             src, ok ? 16 : 0);
    }
    #pragma unroll 2
    for (int i = tid; i < 2 * CIN * 8; i += 256) {
        const int buf = i / (CIN * 8);
        const int j   = i % (CIN * 8);
        const int r   = j >> 3, c = j & 7;
        const __nv_bfloat16* src = (buf ? w_lo : w_hi)
            + (size_t)k * CIN * 64 + r * 64 + c * 8;
        cp16(sb + (buf ? OFF_BLO : OFF_BHI) + (uint32_t)(r * LDB + c * 8) * 2,
             src, 16);
    }
    cp_commit();
    cp_wait<0>();
    __syncthreads();

    float acc[2][4][4] = {};
    #pragma unroll
    for (int s = 0; s < KSTEPS; ++s) {
        uint32_t ah[2][4], al[2][4];
        #pragma unroll
        for (int mt = 0; mt < 2; ++mt) {
            const uint32_t off = (uint32_t)((wm + mt * 16 + lrow) * LDA
                                            + s * 16 + lcol8) * 2;
            ldsm_x4(ah[mt], sb + off);
            ldsm_x4(al[mt], sb + OFF_ALO + off);
        }
        uint32_t bh[2][4], bl[2][4];
        #pragma unroll
        for (int p = 0; p < 2; ++p) {
            const uint32_t off = (uint32_t)((s * 16 + lrow) * LDB
                                            + wn + p * 16 + lcol8) * 2;
            ldsm_x4_t(bh[p], sb + OFF_BHI + off);
            ldsm_x4_t(bl[p], sb + OFF_BLO + off);
        }
        #pragma unroll
        for (int mt = 0; mt < 2; ++mt)
            #pragma unroll
            for (int nt = 0; nt < 4; ++nt) {
                const uint32_t* Bh = &bh[nt >> 1][(nt & 1) * 2];
                const uint32_t* Bl = &bl[nt >> 1][(nt & 1) * 2];
                mma_bf16(acc[mt][nt], ah[mt], Bh);
                mma_bf16(acc[mt][nt], ah[mt], Bl);
                mma_bf16(acc[mt][nt], al[mt], Bh);
            }
    }

    #pragma unroll
    for (int mt = 0; mt < 2; ++mt)
        #pragma unroll
        for (int h = 0; h < 2; ++h) {
            const int rl = wm + mt * 16 + h * 8 + (lane >> 2);
            if (tilestart + rl >= tot) continue;
            const int dst = __ldg(&pairdst[q0 + rl]);
            float* out = g_contrib + (size_t)dst * 64;
            #pragma unroll
            for (int nt = 0; nt < 4; ++nt) {
                const int col = wn + nt * 8 + (lane & 3) * 2;
                float2 v;
                v.x = acc[mt][nt][h * 2];
                v.y = acc[mt][nt][h * 2 + 1];
                *(float2*)(out + col) = v;
            }
        }
}

// reduce per-row contributions (contiguous, ascending-tap order)
template <int SHIFT>
__global__ __launch_bounds__(256) void reduce_kernel(
    const float* __restrict__ bias, int n, const int* __restrict__ maskp,
    __nv_bfloat16* __restrict__ o_hi, __nv_bfloat16* __restrict__ o_lo)
{
    const int row = blockIdx.x * 8 + (threadIdx.x >> 5);
    if (row >= n) return;
    const int lane = threadIdx.x & 31;
    const int cnt  = __popc((unsigned)maskp[row]);
    const int c0   = lane * 2;
    const float* src = g_contrib + ((size_t)row << SHIFT) * 64 + c0;
    float s0 = __ldg(&bias[c0]), s1 = __ldg(&bias[c0 + 1]);
    for (int j = 0; j < cnt; ++j) {
        const float2 v = *(const float2*)(src + (size_t)j * 64);
        s0 += v.x; s1 += v.y;
    }
    s0 = s0 >= 0.f ? s0 : 0.1f * s0;
    s1 = s1 >= 0.f ? s1 : 0.1f * s1;
    __nv_bfloat162 hh, ll;
    hh.x = __float2bfloat16_rn(s0);
    hh.y = __float2bfloat16_rn(s1);
    ll.x = __float2bfloat16_rn(s0 - __bfloat162float(hh.x));
    ll.y = __float2bfloat16_rn(s1 - __bfloat162float(hh.y));
    *(uint32_t*)(o_hi + (size_t)row * 64 + c0) = *(uint32_t*)&hh;
    *(uint32_t*)(o_lo + (size_t)row * 64 + c0) = *(uint32_t*)&ll;
}

// ===========================================================================
// Dense gather-GEMM (conv3): 2-stage cp.async pipeline, 8 warps (4x2)
// ===========================================================================
template <int CIN, int KT>
__global__ __launch_bounds__(256) void sconv_dense(
    const __nv_bfloat16* __restrict__ a_hi, const __nv_bfloat16* __restrict__ a_lo,
    int n_in, const int* __restrict__ nmap, int n_out,
    const __nv_bfloat16* __restrict__ w_hi, const __nv_bfloat16* __restrict__ w_lo,
    const float* __restrict__ bias, float* __restrict__ o_f32)
{
    constexpr int LDA = CIN + 8;
    constexpr int LDB = 72;
    constexpr int KSTEPS = CIN / 16;
    constexpr int CPR = CIN / 8;
    constexpr int A_HALVES = 128 * LDA;
    constexpr int B_HALVES = CIN * LDB;
    constexpr uint32_t OFF_ALO = (uint32_t)A_HALVES * 2;
    constexpr uint32_t OFF_BHI = (uint32_t)(2 * A_HALVES) * 2;
    constexpr uint32_t OFF_BLO = (uint32_t)(2 * A_HALVES + B_HALVES) * 2;
    constexpr uint32_t STAGE   = (uint32_t)(2 * A_HALVES + 2 * B_HALVES) * 2;

    extern __shared__ __align__(16) __nv_bfloat16 smem[];
    const uint32_t sb = smem_u32(smem);

    const int tid  = threadIdx.x;
    const int wid  = tid >> 5;
    const int lane = tid & 31;
    const int row0 = blockIdx.x * 128;
    const int wm   = (wid >> 1) * 32;
    const int wn   = (wid & 1) * 32;
    const int lrow = lane & 15, lcol8 = (lane >> 4) * 8;

    float acc[2][4][4] = {};

    auto prefetch = [&](int t, uint32_t stoff) {
        #pragma unroll 2
        for (int i = tid; i < 2 * 128 * CPR; i += 256) {
            const int buf = i / (128 * CPR);
            const int j   = i % (128 * CPR);
            const int r   = j / CPR, c = j % CPR;
            const int rr  = row0 + r;
            int idx = n_in;
            if (rr < n_out) idx = __ldg(&nmap[(size_t)rr * KT + t]);
            const int ok = idx < n_in;
            const __nv_bfloat16* src = (buf ? a_lo : a_hi)
                + (size_t)(ok ? idx : 0) * CIN + c * 8;
            cp16(sb + stoff + (buf ? OFF_ALO : 0u)
                 + (uint32_t)(r * LDA + c * 8) * 2, src, ok ? 16 : 0);
        }
        #pragma unroll 2
        for (int i = tid; i < 2 * CIN * 8; i += 256) {
            const int buf = i / (CIN * 8);
            const int j   = i % (CIN * 8);
            const int r   = j >> 3, c = j & 7;
            const __nv_bfloat16* src = (buf ? w_lo : w_hi)
                + (size_t)t * CIN * 64 + r * 64 + c * 8;
            cp16(sb + stoff + (buf ? OFF_BLO : OFF_BHI)
                 + (uint32_t)(r * LDB + c * 8) * 2, src, 16);
        }
    };

    prefetch(0, 0);
    cp_commit();

    for (int t = 0; t < KT; ++t) {
        const uint32_t stoff = (t & 1) ? STAGE : 0u;
        if (t + 1 < KT) {
            prefetch(t + 1, (t & 1) ? 0u : STAGE);
            cp_commit();
            cp_wait<1>();
        } else {
            cp_wait<0>();
        }
        __syncthreads();

        #pragma unroll
        for (int s = 0; s < KSTEPS; ++s) {
            uint32_t ah[2][4], al[2][4];
            #pragma unroll
            for (int mt = 0; mt < 2; ++mt) {
                const uint32_t off = (uint32_t)((wm + mt * 16 + lrow) * LDA
                                                + s * 16 + lcol8) * 2;
                ldsm_x4(ah[mt], sb + stoff + off);
                ldsm_x4(al[mt], sb + stoff + OFF_ALO + off);
            }
            uint32_t bh[2][4], bl[2][4];
            #pragma unroll
            for (int p = 0; p < 2; ++p) {
                const uint32_t off = (uint32_t)((s * 16 + lrow) * LDB
                                                + wn + p * 16 + lcol8) * 2;
                ldsm_x4_t(bh[p], sb + stoff + OFF_BHI + off);
                ldsm_x4_t(bl[p], sb + stoff + OFF_BLO + off);
            }
            #pragma unroll
            for (int mt = 0; mt < 2; ++mt)
                #pragma unroll
                for (int nt = 0; nt < 4; ++nt) {
                    const uint32_t* Bh = &bh[nt >> 1][(nt & 1) * 2];
                    const uint32_t* Bl = &bl[nt >> 1][(nt & 1) * 2];
                    mma_bf16(acc[mt][nt], ah[mt], Bh);
                    mma_bf16(acc[mt][nt], ah[mt], Bl);
                    mma_bf16(acc[mt][nt], al[mt], Bh);
                }
        }
        __syncthreads();
    }

    #pragma unroll
    for (int mt = 0; mt < 2; ++mt)
        #pragma unroll
        for (int nt = 0; nt < 4; ++nt)
            #pragma unroll
            for (int h = 0; h < 2; ++h) {
                const int row = row0 + wm + mt * 16 + h * 8 + (lane >> 2);
                if (row >= n_out) continue;
                const int col = wn + nt * 8 + (lane & 3) * 2;
                float2 v;
                v.x = acc[mt][nt][h * 2]     + __ldg(&bias[col]);
                v.y = acc[mt][nt][h * 2 + 1] + __ldg(&bias[col + 1]);
                *(float2*)(o_f32 + (size_t)row * 64 + col) = v;
            }
}

// ---------------------------------------------------------------------------
// Merged split: x | W1 | W2 | W3 -> bf16 hi/lo.  Also zeroes tap counters.
// ---------------------------------------------------------------------------
__global__ __launch_bounds__(256) void splitall_kernel(
    const float* __restrict__ x, __nv_bfloat16* __restrict__ xh, __nv_bfloat16* __restrict__ xl, int nx,
    const float* __restrict__ W1, __nv_bfloat16* __restrict__ h1, __nv_bfloat16* __restrict__ l1, int n1,
    const float* __restrict__ W2, __nv_bfloat16* __restrict__ h2, __nv_bfloat16* __restrict__ l2, int n2,
    const float* __restrict__ W3, __nv_bfloat16* __restrict__ h3, __nv_bfloat16* __restrict__ l3, int n3)
{
    if (blockIdx.x == 0) {
        if (threadIdx.x < KT1) g_tapcnt1[threadIdx.x] = 0;
        else if (threadIdx.x < KT1 + KT2) g_tapcnt2[threadIdx.x - KT1] = 0;
    }
    const int total = nx + n1 + n2 + n3;
    for (int i = blockIdx.x * 256 + threadIdx.x; i < total; i += gridDim.x * 256) {
        const float* s; __nv_bfloat16 *hp, *lp; int j;
        if (i < nx)                { s = x;  hp = xh; lp = xl; j = i; }
        else if (i < nx + n1)      { s = W1; hp = h1; lp = l1; j = i - nx; }
        else if (i < nx + n1 + n2) { s = W2; hp = h2; lp = l2; j = i - nx - n1; }
        else                       { s = W3; hp = h3; lp = l3; j = i - nx - n1 - n2; }
        const float v = s[j];
        const __nv_bfloat16 h = __float2bfloat16_rn(v);
        hp[j] = h;
        lp[j] = __float2bfloat16_rn(v - __bfloat162float(h));
    }
}

__global__ __launch_bounds__(256) void bn_partial_kernel(
    const __nv_bfloat16* __restrict__ fh, const __nv_bfloat16* __restrict__ fl,
    int n2, float* __restrict__ partial)
{
    const int tid = threadIdx.x;
    const int c = tid & 63;
    const int sub = tid >> 6;
    float s = 0.f, s2 = 0.f;
    for (int r = blockIdx.x * 4 + sub; r < n2; r += gridDim.x * 4) {
        const size_t i = (size_t)r * 64 + c;
        const float v = __bfloat162float(fh[i]) + __bfloat162float(fl[i]);
        s += v; s2 += v * v;
    }
    __shared__ float sh[256], sh2[256];
    sh[tid] = s; sh2[tid] = s2;
    __syncthreads();
    if (tid < 64) {
        s  = sh[tid]  + sh[tid + 64]  + sh[tid + 128]  + sh[tid + 192];
        s2 = sh2[tid] + sh2[tid + 64] + sh2[tid + 128] + sh2[tid + 192];
        partial[blockIdx.x * 128 + tid]      = s;
        partial[blockIdx.x * 128 + 64 + tid] = s2;
    }
}

__global__ void bn_finalize_kernel(
    const float* __restrict__ partial, int G, int n2,
    const float* __restrict__ gamma, const float* __restrict__ beta,
    const float* __restrict__ scale, float* __restrict__ st)
{
    const int c = threadIdx.x;
    float s = 0.f, s2 = 0.f;
    for (int g = 0; g < G; ++g) {
        s  += partial[g * 128 + c];
        s2 += partial[g * 128 + 64 + c];
    }
    const float inv_n = 1.0f / (float)n2;
    const float mu  = s * inv_n;
    const float var = fmaxf(s2 * inv_n - mu * mu, 0.f);
    const float r   = rsqrtf(var + 1e-5f);
    const float sc  = scale[0];
    st[c]      = gamma[c] * r * sc;
    st[64 + c] = (beta[c] - mu * gamma[c] * r) * sc;
}

__global__ __launch_bounds__(256) void bn_apply_kernel(
    __nv_bfloat16* __restrict__ fh, __nv_bfloat16* __restrict__ fl,
    int n2, const float* __restrict__ st)
{
    const int i = blockIdx.x * 256 + threadIdx.x;
    if (i < n2 * 64) {
        const int c = i & 63;
        const float v = fmaf(__bfloat162float(fh[i]) + __bfloat162float(fl[i]),
                             st[c], st[64 + c]);
        const __nv_bfloat16 h = __float2bfloat16_rn(v);
        fh[i] = h;
        fl[i] = __float2bfloat16_rn(v - __bfloat162float(h));
    }
}

// ---------------------------------------------------------------------------
extern "C" void kernel_launch(void* const* d_in, const int* in_sizes, int n_in_arrs,
                              void* d_out, int out_size)
{
    const float* x     = (const float*)d_in[0];
    const float* W1    = (const float*)d_in[1];
    const float* b1    = (const float*)d_in[2];
    const float* W2    = (const float*)d_in[3];
    const float* b2    = (const float*)d_in[4];
    const float* W3    = (const float*)d_in[5];
    const float* b3    = (const float*)d_in[6];
    const float* gamma = (const float*)d_in[7];
    const float* beta  = (const float*)d_in[8];
    const float* scale = (const float*)d_in[9];
    const int* nmap1   = (const int*)d_in[10];
    const int* nmap2   = (const int*)d_in[11];
    const int* nmap3   = (const int*)d_in[12];

    const int N   = in_sizes[0] / 96;
    const int N2  = in_sizes[11] / 8;
    const int NB  = (N + 255) / 256;
    const int NB2 = (N2 + 255) / 256;

    __nv_bfloat16 *xh, *xl, *f1h, *f1l, *f2h, *f2l, *w1h, *w1l, *w2h, *w2l, *w3h, *w3l;
    float *partial, *st;
    int *mask1, *mask2, *tapcnt1, *tapcnt2, *pi1, *pd1, *pi2, *pd2;
    cudaGetSymbolAddress((void**)&xh, g_x_hi);   cudaGetSymbolAddress((void**)&xl, g_x_lo);
    cudaGetSymbolAddress((void**)&f1h, g_f1_hi); cudaGetSymbolAddress((void**)&f1l, g_f1_lo);
    cudaGetSymbolAddress((void**)&f2h, g_f2_hi); cudaGetSymbolAddress((void**)&f2l, g_f2_lo);
    cudaGetSymbolAddress((void**)&w1h, g_w1_hi); cudaGetSymbolAddress((void**)&w1l, g_w1_lo);
    cudaGetSymbolAddress((void**)&w2h, g_w2_hi); cudaGetSymbolAddress((void**)&w2l, g_w2_lo);
    cudaGetSymbolAddress((void**)&w3h, g_w3_hi); cudaGetSymbolAddress((void**)&w3l, g_w3_lo);
    cudaGetSymbolAddress((void**)&partial, g_partial);
    cudaGetSymbolAddress((void**)&st, g_st);
    cudaGetSymbolAddress((void**)&mask1, g_mask1);
    cudaGetSymbolAddress((void**)&mask2, g_mask2);
    cudaGetSymbolAddress((void**)&tapcnt1, g_tapcnt1);
    cudaGetSymbolAddress((void**)&tapcnt2, g_tapcnt2);
    cudaGetSymbolAddress((void**)&pi1, g_pairidx1);
    cudaGetSymbolAddress((void**)&pd1, g_pairdst1);
    cudaGetSymbolAddress((void**)&pi2, g_pairidx2);
    cudaGetSymbolAddress((void**)&pd2, g_pairdst2);

    // prep: merged split (also zeroes both tap counter arrays)
    splitall_kernel<<<512, 256>>>(x, xh, xl, N * 96,
                                  W1, w1h, w1l, 27 * 96 * 64,
                                  W2, w2h, w2l, 8 * 64 * 64,
                                  W3, w3h, w3l, 27 * 64 * 64);

    // ---- compaction preps ----
    emit_fused<KT1, 5><<<NB,  256>>>(nmap1, N,  N, mask1, tapcnt1, pi1, pd1);
    emit_fused<KT2, 3><<<NB2, 256>>>(nmap2, N2, N, mask2, tapcnt2, pi2, pd2);

    // ---- conv1: compacted (27 taps, 96ch) ----
    {
        constexpr int smem = (2 * 128 * 104 + 2 * 96 * 72) * 2;   // 80,896 B
        cudaFuncSetAttribute(conv_compact<96>,
                             cudaFuncAttributeMaxDynamicSharedMemorySize, smem);
        dim3 grid((N + 127) / 128, KT1);
        conv_compact<96><<<grid, 256, smem>>>(xh, xl, w1h, w1l, tapcnt1, pi1, pd1);
    }
    reduce_kernel<5><<<(N + 7) / 8, 256>>>(b1, N, mask1, f1h, f1l);

    // ---- conv2: compacted (8 taps, 64ch) ----
    {
        constexpr int smem = (2 * 128 * 72 + 2 * 64 * 72) * 2;    // 55,296 B
        cudaFuncSetAttribute(conv_compact<64>,
                             cudaFuncAttributeMaxDynamicSharedMemorySize, smem);
        dim3 grid((N2 + 127) / 128, KT2);
        conv_compact<64><<<grid, 256, smem>>>(f1h, f1l, w2h, w2l, tapcnt2, pi2, pd2);
    }
    reduce_kernel<3><<<(N2 + 7) / 8, 256>>>(b2, N2, mask2, f2h, f2l);

    // ---- batch norm + scale ----
    {
        const int G = 120;
        bn_partial_kernel<<<G, 256>>>(f2h, f2l, N2, partial);
        bn_finalize_kernel<<<1, 64>>>(partial, G, N2, gamma, beta, scale, st);
        bn_apply_kernel<<<(N2 * 64 + 255) / 256, 256>>>(f2h, f2l, N2, st);
    }
    // ---- conv3: dense, 27 taps, fp32 out ----
    {
        constexpr int stage = (2 * 128 * 72 + 2 * 64 * 72) * 2;
        constexpr int smem  = 2 * stage;                          // 110,592 B
        cudaFuncSetAttribute(sconv_dense<64, 27>,
                             cudaFuncAttributeMaxDynamicSharedMemorySize, smem);
        sconv_dense<64, 27><<<(N2 + 127) / 128, 256, smem>>>(
            f2h, f2l, N2, nmap3, N2, w3h, w3l, b3, (float*)d_out);
    }
}